// round 2
// baseline (speedup 1.0000x reference)
#include <cuda_runtime.h>
#include <math_constants.h>

#define NN 50000
#define EE 800000
#define CC 128
#define GG 128
#define L0 512
#define L1 256

// ---------------- scratch (static device globals; no allocation) ----------------
__device__ float g_qkvs[(size_t)NN * 512];   // q|k|v|skip per node
__device__ float g_hA[(size_t)NN * CC];
__device__ float g_hB[(size_t)NN * CC];
__device__ int   g_cnt[NN];
__device__ int   g_off[NN + 1];
__device__ int   g_cur[NN];
__device__ int   g_src[EE];
__device__ int   g_eid[EE];
__device__ float g_pool[GG * CC];
__device__ float g_m1[GG * L0];
__device__ float g_m2[GG * L1];

// ---------------- CSR build ----------------
__global__ void k_zero_cnt() {
    int i = blockIdx.x * blockDim.x + threadIdx.x;
    if (i < NN) g_cnt[i] = 0;
}

__global__ void k_count(const int* __restrict__ ei) {
    int e = blockIdx.x * blockDim.x + threadIdx.x;
    if (e < EE) atomicAdd(&g_cnt[ei[EE + e]], 1);
}

// single-block exclusive scan of g_cnt -> g_off (+ copy to g_cur)
__global__ void k_scan() {
    const int T = 1024;
    const int CHUNK = (NN + T - 1) / T;   // 49
    int t = threadIdx.x;
    int base = t * CHUNK;
    int s = 0;
    for (int j = 0; j < CHUNK; j++) {
        int idx = base + j;
        if (idx < NN) s += g_cnt[idx];
    }
    __shared__ int sh[T];
    sh[t] = s;
    __syncthreads();
    for (int d = 1; d < T; d <<= 1) {
        int v = (t >= d) ? sh[t - d] : 0;
        __syncthreads();
        sh[t] += v;
        __syncthreads();
    }
    int run = sh[t] - s;  // exclusive prefix of this chunk
    for (int j = 0; j < CHUNK; j++) {
        int idx = base + j;
        if (idx < NN) {
            g_off[idx] = run;
            g_cur[idx] = run;
            run += g_cnt[idx];
        }
    }
    if (t == T - 1) g_off[NN] = sh[T - 1];
}

__global__ void k_fill(const int* __restrict__ ei) {
    int e = blockIdx.x * blockDim.x + threadIdx.x;
    if (e < EE) {
        int d = ei[EE + e];
        int p = atomicAdd(&g_cur[d], 1);
        g_src[p] = ei[e];
        g_eid[p] = e;
    }
}

// ---------------- layer-0 projection (din = 4) ----------------
__global__ void k_gemm0(const float* __restrict__ x,
                        const float* __restrict__ Wq, const float* __restrict__ bq,
                        const float* __restrict__ Wk, const float* __restrict__ bk,
                        const float* __restrict__ Wv, const float* __restrict__ bv,
                        const float* __restrict__ Ws, const float* __restrict__ bs) {
    long long idx = (long long)blockIdx.x * blockDim.x + threadIdx.x;
    if (idx >= (long long)NN * 512) return;
    int n = (int)(idx >> 9);
    int col = (int)(idx & 511);
    int grp = col >> 7;
    int c = col & 127;
    const float* W; const float* b;
    if      (grp == 0) { W = Wq; b = bq; }
    else if (grp == 1) { W = Wk; b = bk; }
    else if (grp == 2) { W = Wv; b = bv; }
    else               { W = Ws; b = bs; }
    float x0 = x[n * 4 + 0], x1 = x[n * 4 + 1], x2 = x[n * 4 + 2], x3 = x[n * 4 + 3];
    float v = b[c] + x0 * W[c] + x1 * W[128 + c] + x2 * W[256 + c] + x3 * W[384 + c];
    g_qkvs[(size_t)n * 512 + col] = v;
}

// ---------------- main projection GEMM: [NN,128] @ [128,512] ----------------
// 64x64 tile, 256 threads, 4x4 microtile, BK=16
__global__ __launch_bounds__(256) void k_gemm(int inSel,
                        const float* __restrict__ Wq, const float* __restrict__ bq,
                        const float* __restrict__ Wk, const float* __restrict__ bk,
                        const float* __restrict__ Wv, const float* __restrict__ bv,
                        const float* __restrict__ Ws, const float* __restrict__ bs) {
    const float* __restrict__ H = inSel ? g_hB : g_hA;
    __shared__ float As[16 * 68];   // [k][m], padded row stride 68
    __shared__ float Bs[16 * 64];   // [k][n]

    int tid = threadIdx.x;
    int tx = tid & 15, ty = tid >> 4;
    int row0 = blockIdx.y * 64;
    int colTile = blockIdx.x;               // 0..7
    int grp = colTile >> 1;
    int colbase = (colTile & 1) * 64;
    const float* W; const float* b;
    if      (grp == 0) { W = Wq; b = bq; }
    else if (grp == 1) { W = Wk; b = bk; }
    else if (grp == 2) { W = Wv; b = bv; }
    else               { W = Ws; b = bs; }

    float acc[4][4];
#pragma unroll
    for (int i = 0; i < 4; i++)
#pragma unroll
        for (int j = 0; j < 4; j++) acc[i][j] = 0.f;

    int am = tid >> 2;            // 0..63 row within tile
    int ak4 = (tid & 3) * 4;      // k offset (float4)

    for (int kk = 0; kk < 128; kk += 16) {
        // load A tile (transposed into As[k][m])
        float4 a4;
        if (row0 + am < NN)
            a4 = *(const float4*)&H[(size_t)(row0 + am) * 128 + kk + ak4];
        else
            a4 = make_float4(0.f, 0.f, 0.f, 0.f);
        As[(ak4 + 0) * 68 + am] = a4.x;
        As[(ak4 + 1) * 68 + am] = a4.y;
        As[(ak4 + 2) * 68 + am] = a4.z;
        As[(ak4 + 3) * 68 + am] = a4.w;
        // load B tile
#pragma unroll
        for (int l = 0; l < 4; l++) {
            int idx = tid + l * 256;
            int k = idx >> 6, n = idx & 63;
            Bs[k * 64 + n] = W[(size_t)(kk + k) * 128 + colbase + n];
        }
        __syncthreads();
#pragma unroll
        for (int k = 0; k < 16; k++) {
            float4 a = *(const float4*)&As[k * 68 + ty * 4];
            float4 bb = *(const float4*)&Bs[k * 64 + tx * 4];
            float ar[4] = {a.x, a.y, a.z, a.w};
            float br[4] = {bb.x, bb.y, bb.z, bb.w};
#pragma unroll
            for (int i = 0; i < 4; i++)
#pragma unroll
                for (int j = 0; j < 4; j++) acc[i][j] += ar[i] * br[j];
        }
        __syncthreads();
    }

    int outcolbase = grp * 128 + colbase + tx * 4;
    float4 bias = *(const float4*)&b[colbase + tx * 4];
    float bb[4] = {bias.x, bias.y, bias.z, bias.w};
#pragma unroll
    for (int i = 0; i < 4; i++) {
        int r = row0 + ty * 4 + i;
        if (r < NN) {
            float4 o;
            o.x = acc[i][0] + bb[0];
            o.y = acc[i][1] + bb[1];
            o.z = acc[i][2] + bb[2];
            o.w = acc[i][3] + bb[3];
            *(float4*)&g_qkvs[(size_t)r * 512 + outcolbase] = o;
        }
    }
}

// ---------------- edge aggregation: warp per dst node, online softmax ----------------
__global__ __launch_bounds__(256) void k_agg(const float* __restrict__ ea,
                                             const float* __restrict__ We,
                                             int outSel) {
    __shared__ float sWe[384];
    for (int i = threadIdx.x; i < 384; i += 256) sWe[i] = We[i];
    __syncthreads();

    int warp = blockIdx.x * 8 + (threadIdx.x >> 5);
    if (warp >= NN) return;
    int lane = threadIdx.x & 31;
    int node = warp;

    const float* __restrict__ q = &g_qkvs[(size_t)node * 512];
    float qv[4];
#pragma unroll
    for (int j = 0; j < 4; j++) qv[j] = q[lane + 32 * j];

    float m = -CUDART_INF_F, den = 0.f;
    float acc[4] = {0.f, 0.f, 0.f, 0.f};

    int beg = __ldg(&g_off[node]), end = __ldg(&g_off[node + 1]);
    for (int p = beg; p < end; p++) {
        int src = __ldg(&g_src[p]);
        int eid = __ldg(&g_eid[p]);
        float ea0 = __ldg(&ea[eid * 3 + 0]);
        float ea1 = __ldg(&ea[eid * 3 + 1]);
        float ea2 = __ldg(&ea[eid * 3 + 2]);
        const float* __restrict__ kb = &g_qkvs[(size_t)src * 512 + 128];
        const float* __restrict__ vb = &g_qkvs[(size_t)src * 512 + 256];
        float ev[4];
        float dot = 0.f;
#pragma unroll
        for (int j = 0; j < 4; j++) {
            int c = lane + 32 * j;
            float e = ea0 * sWe[c] + ea1 * sWe[128 + c] + ea2 * sWe[256 + c];
            ev[j] = e;
            dot += qv[j] * (kb[c] + e);
        }
#pragma unroll
        for (int o = 16; o > 0; o >>= 1) dot += __shfl_xor_sync(0xffffffffu, dot, o);
        float logit = dot * 0.08838834764831845f;  // 1/sqrt(128)
        float nm = fmaxf(m, logit);
        float corr = __expf(m - nm);
        float w = __expf(logit - nm);
        den = den * corr + w;
#pragma unroll
        for (int j = 0; j < 4; j++) {
            int c = lane + 32 * j;
            acc[j] = acc[j] * corr + w * (vb[c] + ev[j]);
        }
        m = nm;
    }

    float inv = den > 0.f ? 1.f / den : 0.f;
    float* __restrict__ out = outSel ? g_hB : g_hA;
#pragma unroll
    for (int j = 0; j < 4; j++) {
        int c = lane + 32 * j;
        float o = acc[j] * inv + q[384 + c];     // skip (x@Ws+bs) precomputed
        o = o > 0.f ? o : 0.01f * o;             // leaky_relu
        out[(size_t)node * CC + c] = o;
    }
}

// ---------------- pooling ----------------
__global__ void k_zero_pool() {
    int i = blockIdx.x * blockDim.x + threadIdx.x;
    if (i < GG * CC) g_pool[i] = 0.f;
}

__global__ void k_pool(const int* __restrict__ batch, int hSel) {
    long long idx = (long long)blockIdx.x * blockDim.x + threadIdx.x;
    if (idx >= (long long)NN * CC) return;
    int n = (int)(idx >> 7);
    int c = (int)(idx & 127);
    const float* h = hSel ? g_hB : g_hA;
    atomicAdd(&g_pool[batch[n] * CC + c], h[idx]);
}

// ---------------- MLP head ----------------
__global__ void k_mlp1(const float* __restrict__ W, const float* __restrict__ b) {
    int idx = blockIdx.x * blockDim.x + threadIdx.x;
    if (idx >= GG * L0) return;
    int r = idx >> 9, c = idx & (L0 - 1);
    float s = b[c];
    for (int k = 0; k < CC; k++) s += g_pool[r * CC + k] * W[k * L0 + c];
    g_m1[idx] = s > 0.f ? s : 0.f;
}

__global__ void k_mlp2(const float* __restrict__ W, const float* __restrict__ b) {
    int idx = blockIdx.x * blockDim.x + threadIdx.x;
    if (idx >= GG * L1) return;
    int r = idx >> 8, c = idx & (L1 - 1);
    float s = b[c];
    for (int k = 0; k < L0; k++) s += g_m1[r * L0 + k] * W[k * L1 + c];
    g_m2[idx] = s > 0.f ? s : 0.f;
}

__global__ void k_mlp3(const float* __restrict__ W, const float* __restrict__ b,
                       float* __restrict__ out) {
    int idx = threadIdx.x;
    if (idx >= GG * 2) return;
    int r = idx >> 1, c = idx & 1;
    float s = b[c];
    for (int k = 0; k < L1; k++) s += g_m2[r * L1 + k] * W[k * 2 + c];
    out[idx] = s;
}

// ---------------- launch ----------------
extern "C" void kernel_launch(void* const* d_in, const int* in_sizes, int n_in,
                              void* d_out, int out_size) {
    const float* x     = (const float*)d_in[0];
    const int*   ei    = (const int*)d_in[1];
    const float* ea    = (const float*)d_in[2];
    const int*   batch = (const int*)d_in[3];
    const float* Wq0 = (const float*)d_in[4];  const float* bq0 = (const float*)d_in[5];
    const float* Wk0 = (const float*)d_in[6];  const float* bk0 = (const float*)d_in[7];
    const float* Wv0 = (const float*)d_in[8];  const float* bv0 = (const float*)d_in[9];
    const float* We0 = (const float*)d_in[10];
    const float* Ws0 = (const float*)d_in[11]; const float* bs0 = (const float*)d_in[12];
    const float* Wq1 = (const float*)d_in[13]; const float* bq1 = (const float*)d_in[14];
    const float* Wk1 = (const float*)d_in[15]; const float* bk1 = (const float*)d_in[16];
    const float* Wv1 = (const float*)d_in[17]; const float* bv1 = (const float*)d_in[18];
    const float* We1 = (const float*)d_in[19];
    const float* Ws1 = (const float*)d_in[20]; const float* bs1 = (const float*)d_in[21];
    const float* Wl0 = (const float*)d_in[22]; const float* bl0 = (const float*)d_in[23];
    const float* Wl1 = (const float*)d_in[24]; const float* bl1 = (const float*)d_in[25];
    const float* Wl2 = (const float*)d_in[26]; const float* bl2 = (const float*)d_in[27];
    float* out = (float*)d_out;

    // CSR build (by dst)
    k_zero_cnt<<<(NN + 255) / 256, 256>>>();
    k_count<<<(EE + 255) / 256, 256>>>(ei);
    k_scan<<<1, 1024>>>();
    k_fill<<<(EE + 255) / 256, 256>>>(ei);

    dim3 gemmGrid(8, (NN + 63) / 64);

    // layer 0
    k_gemm0<<<(int)(((long long)NN * 512 + 255) / 256), 256>>>(x, Wq0, bq0, Wk0, bk0, Wv0, bv0, Ws0, bs0);
    k_agg<<<(NN + 7) / 8, 256>>>(ea, We0, 0);          // -> hA
    // layer 1 (shared weights)
    k_gemm<<<gemmGrid, 256>>>(0, Wq1, bq1, Wk1, bk1, Wv1, bv1, Ws1, bs1);
    k_agg<<<(NN + 7) / 8, 256>>>(ea, We1, 1);          // -> hB
    // layer 2 (same weights)
    k_gemm<<<gemmGrid, 256>>>(1, Wq1, bq1, Wk1, bk1, Wv1, bv1, Ws1, bs1);
    k_agg<<<(NN + 7) / 8, 256>>>(ea, We1, 0);          // -> hA

    // global add pool
    k_zero_pool<<<(GG * CC + 255) / 256, 256>>>();
    k_pool<<<(int)(((long long)NN * CC + 255) / 256), 256>>>(batch, 0);

    // MLP head
    k_mlp1<<<(GG * L0 + 255) / 256, 256>>>(Wl0, bl0);
    k_mlp2<<<(GG * L1 + 255) / 256, 256>>>(Wl1, bl1);
    k_mlp3<<<1, 256>>>(Wl2, bl2, out);
}

// round 3
// speedup vs baseline: 1.0581x; 1.0581x over previous
#include <cuda_runtime.h>
#include <math_constants.h>

#define NN 50000
#define EE 800000
#define CC 128
#define GG 128
#define L0 512
#define L1 256

// ---------------- scratch (static device globals; no allocation) ----------------
__device__ float g_qkvs[(size_t)NN * 512];   // q|k|v|skip per node
__device__ float g_hA[(size_t)NN * CC];
__device__ float g_hB[(size_t)NN * CC];
__device__ int   g_cnt[NN];
__device__ int   g_off[NN + 1];
__device__ int   g_cur[NN];
__device__ int   g_src[EE];
__device__ int   g_eid[EE];
__device__ float g_pool[GG * CC];
__device__ float g_m1[GG * L0];
__device__ float g_m2[GG * L1];

// ---------------- packed f32x2 helpers ----------------
__device__ __forceinline__ unsigned long long rep2(float x) {
    unsigned long long r;
    asm("mov.b64 %0, {%1, %1};" : "=l"(r) : "f"(x));
    return r;
}
#define FFMA_X2(acc, a, b) asm("fma.rn.f32x2 %0, %1, %2, %0;" : "+l"(acc) : "l"(a), "l"(b))

union U64F2 { unsigned long long u; float2 f; };

// ---------------- CSR build ----------------
__global__ void k_zero_cnt() {
    int i = blockIdx.x * blockDim.x + threadIdx.x;
    if (i < NN) g_cnt[i] = 0;
    if (i < GG * CC) g_pool[i] = 0.f;
}

__global__ void k_count(const int* __restrict__ ei) {
    int e = blockIdx.x * blockDim.x + threadIdx.x;
    if (e < EE) atomicAdd(&g_cnt[ei[EE + e]], 1);
}

// single-block exclusive scan of g_cnt -> g_off (+ copy to g_cur)
__global__ void k_scan() {
    const int T = 1024;
    const int CHUNK = (NN + T - 1) / T;   // 49
    int t = threadIdx.x;
    int base = t * CHUNK;
    int s = 0;
    for (int j = 0; j < CHUNK; j++) {
        int idx = base + j;
        if (idx < NN) s += g_cnt[idx];
    }
    __shared__ int sh[T];
    sh[t] = s;
    __syncthreads();
    for (int d = 1; d < T; d <<= 1) {
        int v = (t >= d) ? sh[t - d] : 0;
        __syncthreads();
        sh[t] += v;
        __syncthreads();
    }
    int run = sh[t] - s;  // exclusive prefix of this chunk
    for (int j = 0; j < CHUNK; j++) {
        int idx = base + j;
        if (idx < NN) {
            g_off[idx] = run;
            g_cur[idx] = run;
            run += g_cnt[idx];
        }
    }
    if (t == T - 1) g_off[NN] = sh[T - 1];
}

__global__ void k_fill(const int* __restrict__ ei) {
    int e = blockIdx.x * blockDim.x + threadIdx.x;
    if (e < EE) {
        int d = ei[EE + e];
        int p = atomicAdd(&g_cur[d], 1);
        g_src[p] = ei[e];
        g_eid[p] = e;
    }
}

// ---------------- layer-0 projection (din = 4) ----------------
__global__ void k_gemm0(const float* __restrict__ x,
                        const float* __restrict__ Wq, const float* __restrict__ bq,
                        const float* __restrict__ Wk, const float* __restrict__ bk,
                        const float* __restrict__ Wv, const float* __restrict__ bv,
                        const float* __restrict__ Ws, const float* __restrict__ bs) {
    long long idx = (long long)blockIdx.x * blockDim.x + threadIdx.x;
    if (idx >= (long long)NN * 512) return;
    int n = (int)(idx >> 9);
    int col = (int)(idx & 511);
    int grp = col >> 7;
    int c = col & 127;
    const float* W; const float* b;
    if      (grp == 0) { W = Wq; b = bq; }
    else if (grp == 1) { W = Wk; b = bk; }
    else if (grp == 2) { W = Wv; b = bv; }
    else               { W = Ws; b = bs; }
    float x0 = x[n * 4 + 0], x1 = x[n * 4 + 1], x2 = x[n * 4 + 2], x3 = x[n * 4 + 3];
    float v = b[c] + x0 * W[c] + x1 * W[128 + c] + x2 * W[256 + c] + x3 * W[384 + c];
    g_qkvs[(size_t)n * 512 + col] = v;
}

// ---------------- main projection GEMM: [NN,128] @ [128,512] ----------------
// 128x64 tile, 256 threads, 8x4 microtile, BK=16, packed f32x2 FMA (M-pairs)
#define AS_STRIDE 132
__global__ __launch_bounds__(256) void k_gemm(int inSel,
                        const float* __restrict__ Wq, const float* __restrict__ bq,
                        const float* __restrict__ Wk, const float* __restrict__ bk,
                        const float* __restrict__ Wv, const float* __restrict__ bv,
                        const float* __restrict__ Ws, const float* __restrict__ bs) {
    const float* __restrict__ H = inSel ? g_hB : g_hA;
    __shared__ __align__(16) float As[16 * AS_STRIDE];  // [k][m], m=0..127
    __shared__ __align__(16) float Bs[16 * 64];         // [k][n], n=0..63

    int tid = threadIdx.x;
    int tx = tid & 15;          // 16 col groups of 4
    int ty = tid >> 4;          // 16 row groups of 8
    int row0 = blockIdx.y * 128;
    int colTile = blockIdx.x;   // 0..7
    int grp = colTile >> 1;
    int colbase = (colTile & 1) * 64;
    const float* W; const float* b;
    if      (grp == 0) { W = Wq; b = bq; }
    else if (grp == 1) { W = Wk; b = bk; }
    else if (grp == 2) { W = Wv; b = bv; }
    else               { W = Ws; b = bs; }

    unsigned long long acc[4][4];   // [ipair][j]; lo=row 2*ip, hi=row 2*ip+1
#pragma unroll
    for (int i = 0; i < 4; i++)
#pragma unroll
        for (int j = 0; j < 4; j++) acc[i][j] = 0ULL;

    int am = tid >> 1;            // 0..127 row within tile
    int ak = (tid & 1) * 8;       // k offset (8 floats = 2 float4)

    for (int kk = 0; kk < 128; kk += 16) {
        // load A tile (transposed into As[k][m]): 128 rows x 16 k
        float av[8];
        if (row0 + am < NN) {
            float4 a0 = *(const float4*)&H[(size_t)(row0 + am) * 128 + kk + ak];
            float4 a1 = *(const float4*)&H[(size_t)(row0 + am) * 128 + kk + ak + 4];
            av[0] = a0.x; av[1] = a0.y; av[2] = a0.z; av[3] = a0.w;
            av[4] = a1.x; av[5] = a1.y; av[6] = a1.z; av[7] = a1.w;
        } else {
#pragma unroll
            for (int t = 0; t < 8; t++) av[t] = 0.f;
        }
#pragma unroll
        for (int t = 0; t < 8; t++) As[(ak + t) * AS_STRIDE + am] = av[t];
        // load B tile: 16 k x 64 n
        {
            int bk = tid >> 4;          // 0..15
            int bn = (tid & 15) * 4;    // 0..60
            *(float4*)&Bs[bk * 64 + bn] =
                *(const float4*)&W[(size_t)(kk + bk) * 128 + colbase + bn];
        }
        __syncthreads();
#pragma unroll
        for (int k = 0; k < 16; k++) {
            ulonglong2 a01 = *(const ulonglong2*)&As[k * AS_STRIDE + ty * 8];
            ulonglong2 a23 = *(const ulonglong2*)&As[k * AS_STRIDE + ty * 8 + 4];
            float4 b4 = *(const float4*)&Bs[k * 64 + tx * 4];
            unsigned long long ap[4] = {a01.x, a01.y, a23.x, a23.y};
            unsigned long long br[4] = {rep2(b4.x), rep2(b4.y), rep2(b4.z), rep2(b4.w)};
#pragma unroll
            for (int ip = 0; ip < 4; ip++)
#pragma unroll
                for (int j = 0; j < 4; j++) FFMA_X2(acc[ip][j], ap[ip], br[j]);
        }
        __syncthreads();
    }

    int outcolbase = grp * 128 + colbase + tx * 4;
    float4 bias = *(const float4*)&b[colbase + tx * 4];
    float bb[4] = {bias.x, bias.y, bias.z, bias.w};
#pragma unroll
    for (int ip = 0; ip < 4; ip++) {
        U64F2 c0, c1, c2, c3;
        c0.u = acc[ip][0]; c1.u = acc[ip][1]; c2.u = acc[ip][2]; c3.u = acc[ip][3];
        int rlo = row0 + ty * 8 + 2 * ip;
        if (rlo < NN) {
            float4 o;
            o.x = c0.f.x + bb[0]; o.y = c1.f.x + bb[1];
            o.z = c2.f.x + bb[2]; o.w = c3.f.x + bb[3];
            *(float4*)&g_qkvs[(size_t)rlo * 512 + outcolbase] = o;
        }
        int rhi = rlo + 1;
        if (rhi < NN) {
            float4 o;
            o.x = c0.f.y + bb[0]; o.y = c1.f.y + bb[1];
            o.z = c2.f.y + bb[2]; o.w = c3.f.y + bb[3];
            *(float4*)&g_qkvs[(size_t)rhi * 512 + outcolbase] = o;
        }
    }
}

// ---------------- edge aggregation: warp per dst node, online softmax, 2-edge unroll ----------------
__global__ __launch_bounds__(256) void k_agg(const float* __restrict__ ea,
                                             const float* __restrict__ We,
                                             int outSel) {
    __shared__ float sWe[384];
    for (int i = threadIdx.x; i < 384; i += 256) sWe[i] = We[i];
    __syncthreads();

    int node = blockIdx.x * 8 + (threadIdx.x >> 5);
    if (node >= NN) return;
    int lane = threadIdx.x & 31;

    const float* __restrict__ q = &g_qkvs[(size_t)node * 512];
    float qv[4];
#pragma unroll
    for (int j = 0; j < 4; j++) qv[j] = q[lane + 32 * j];

    float m = -CUDART_INF_F, den = 0.f;
    float acc[4] = {0.f, 0.f, 0.f, 0.f};
    const float scale = 0.08838834764831845f;  // 1/sqrt(128)

    int beg = __ldg(&g_off[node]), end = __ldg(&g_off[node + 1]);
    int p = beg;
    for (; p + 2 <= end; p += 2) {
        int s0 = __ldg(&g_src[p]),     s1 = __ldg(&g_src[p + 1]);
        int e0 = __ldg(&g_eid[p]),     e1 = __ldg(&g_eid[p + 1]);
        float a00 = __ldg(&ea[e0 * 3 + 0]), a01 = __ldg(&ea[e0 * 3 + 1]), a02 = __ldg(&ea[e0 * 3 + 2]);
        float a10 = __ldg(&ea[e1 * 3 + 0]), a11 = __ldg(&ea[e1 * 3 + 1]), a12 = __ldg(&ea[e1 * 3 + 2]);
        const float* __restrict__ k0 = &g_qkvs[(size_t)s0 * 512 + 128];
        const float* __restrict__ k1 = &g_qkvs[(size_t)s1 * 512 + 128];
        float kv0[4], kv1[4], vv0[4], vv1[4], ev0[4], ev1[4];
        float d0 = 0.f, d1 = 0.f;
#pragma unroll
        for (int j = 0; j < 4; j++) {
            int c = lane + 32 * j;
            kv0[j] = k0[c]; vv0[j] = k0[c + 128];
            kv1[j] = k1[c]; vv1[j] = k1[c + 128];
            ev0[j] = a00 * sWe[c] + a01 * sWe[128 + c] + a02 * sWe[256 + c];
            ev1[j] = a10 * sWe[c] + a11 * sWe[128 + c] + a12 * sWe[256 + c];
            d0 += qv[j] * (kv0[j] + ev0[j]);
            d1 += qv[j] * (kv1[j] + ev1[j]);
        }
#pragma unroll
        for (int o = 16; o > 0; o >>= 1) {
            d0 += __shfl_xor_sync(0xffffffffu, d0, o);
            d1 += __shfl_xor_sync(0xffffffffu, d1, o);
        }
        float l0 = d0 * scale, l1 = d1 * scale;
        float nm = fmaxf(m, fmaxf(l0, l1));
        float corr = __expf(m - nm);
        float w0 = __expf(l0 - nm);
        float w1 = __expf(l1 - nm);
        den = den * corr + w0 + w1;
#pragma unroll
        for (int j = 0; j < 4; j++)
            acc[j] = acc[j] * corr + w0 * (vv0[j] + ev0[j]) + w1 * (vv1[j] + ev1[j]);
        m = nm;
    }
    if (p < end) {
        int s0 = __ldg(&g_src[p]);
        int e0 = __ldg(&g_eid[p]);
        float a00 = __ldg(&ea[e0 * 3 + 0]), a01 = __ldg(&ea[e0 * 3 + 1]), a02 = __ldg(&ea[e0 * 3 + 2]);
        const float* __restrict__ k0 = &g_qkvs[(size_t)s0 * 512 + 128];
        float kv0[4], vv0[4], ev0[4];
        float d0 = 0.f;
#pragma unroll
        for (int j = 0; j < 4; j++) {
            int c = lane + 32 * j;
            kv0[j] = k0[c]; vv0[j] = k0[c + 128];
            ev0[j] = a00 * sWe[c] + a01 * sWe[128 + c] + a02 * sWe[256 + c];
            d0 += qv[j] * (kv0[j] + ev0[j]);
        }
#pragma unroll
        for (int o = 16; o > 0; o >>= 1) d0 += __shfl_xor_sync(0xffffffffu, d0, o);
        float l0 = d0 * scale;
        float nm = fmaxf(m, l0);
        float corr = __expf(m - nm);
        float w0 = __expf(l0 - nm);
        den = den * corr + w0;
#pragma unroll
        for (int j = 0; j < 4; j++)
            acc[j] = acc[j] * corr + w0 * (vv0[j] + ev0[j]);
        m = nm;
    }

    float inv = den > 0.f ? 1.f / den : 0.f;
    float* __restrict__ out = outSel ? g_hB : g_hA;
#pragma unroll
    for (int j = 0; j < 4; j++) {
        int c = lane + 32 * j;
        float o = acc[j] * inv + q[384 + c];     // skip (x@Ws+bs) precomputed
        o = o > 0.f ? o : 0.01f * o;             // leaky_relu
        out[(size_t)node * CC + c] = o;
    }
}

// ---------------- pooling ----------------
__global__ void k_pool(const int* __restrict__ batch, int hSel) {
    long long idx = (long long)blockIdx.x * blockDim.x + threadIdx.x;
    if (idx >= (long long)NN * CC) return;
    int n = (int)(idx >> 7);
    int c = (int)(idx & 127);
    const float* h = hSel ? g_hB : g_hA;
    atomicAdd(&g_pool[batch[n] * CC + c], h[idx]);
}

// ---------------- MLP head ----------------
__global__ void k_mlp1(const float* __restrict__ W, const float* __restrict__ b) {
    int idx = blockIdx.x * blockDim.x + threadIdx.x;
    if (idx >= GG * L0) return;
    int r = idx >> 9, c = idx & (L0 - 1);
    float s = b[c];
    for (int k = 0; k < CC; k++) s += g_pool[r * CC + k] * W[k * L0 + c];
    g_m1[idx] = s > 0.f ? s : 0.f;
}

__global__ void k_mlp2(const float* __restrict__ W, const float* __restrict__ b) {
    int idx = blockIdx.x * blockDim.x + threadIdx.x;
    if (idx >= GG * L1) return;
    int r = idx >> 8, c = idx & (L1 - 1);
    float s = b[c];
    for (int k = 0; k < L0; k++) s += g_m1[r * L0 + k] * W[k * L1 + c];
    g_m2[idx] = s > 0.f ? s : 0.f;
}

__global__ void k_mlp3(const float* __restrict__ W, const float* __restrict__ b,
                       float* __restrict__ out) {
    int idx = threadIdx.x;
    if (idx >= GG * 2) return;
    int r = idx >> 1, c = idx & 1;
    float s = b[c];
    for (int k = 0; k < L1; k++) s += g_m2[r * L1 + k] * W[k * 2 + c];
    out[idx] = s;
}

// ---------------- launch ----------------
extern "C" void kernel_launch(void* const* d_in, const int* in_sizes, int n_in,
                              void* d_out, int out_size) {
    const float* x     = (const float*)d_in[0];
    const int*   ei    = (const int*)d_in[1];
    const float* ea    = (const float*)d_in[2];
    const int*   batch = (const int*)d_in[3];
    const float* Wq0 = (const float*)d_in[4];  const float* bq0 = (const float*)d_in[5];
    const float* Wk0 = (const float*)d_in[6];  const float* bk0 = (const float*)d_in[7];
    const float* Wv0 = (const float*)d_in[8];  const float* bv0 = (const float*)d_in[9];
    const float* We0 = (const float*)d_in[10];
    const float* Ws0 = (const float*)d_in[11]; const float* bs0 = (const float*)d_in[12];
    const float* Wq1 = (const float*)d_in[13]; const float* bq1 = (const float*)d_in[14];
    const float* Wk1 = (const float*)d_in[15]; const float* bk1 = (const float*)d_in[16];
    const float* Wv1 = (const float*)d_in[17]; const float* bv1 = (const float*)d_in[18];
    const float* We1 = (const float*)d_in[19];
    const float* Ws1 = (const float*)d_in[20]; const float* bs1 = (const float*)d_in[21];
    const float* Wl0 = (const float*)d_in[22]; const float* bl0 = (const float*)d_in[23];
    const float* Wl1 = (const float*)d_in[24]; const float* bl1 = (const float*)d_in[25];
    const float* Wl2 = (const float*)d_in[26]; const float* bl2 = (const float*)d_in[27];
    float* out = (float*)d_out;

    // CSR build (by dst)  + zero pool
    k_zero_cnt<<<(NN + 255) / 256, 256>>>();
    k_count<<<(EE + 255) / 256, 256>>>(ei);
    k_scan<<<1, 1024>>>();
    k_fill<<<(EE + 255) / 256, 256>>>(ei);

    dim3 gemmGrid(8, (NN + 127) / 128);

    // layer 0
    k_gemm0<<<(int)(((long long)NN * 512 + 255) / 256), 256>>>(x, Wq0, bq0, Wk0, bk0, Wv0, bv0, Ws0, bs0);
    k_agg<<<(NN + 7) / 8, 256>>>(ea, We0, 0);          // -> hA
    // layer 1 (shared weights)
    k_gemm<<<gemmGrid, 256>>>(0, Wq1, bq1, Wk1, bk1, Wv1, bv1, Ws1, bs1);
    k_agg<<<(NN + 7) / 8, 256>>>(ea, We1, 1);          // -> hB
    // layer 2 (same weights)
    k_gemm<<<gemmGrid, 256>>>(1, Wq1, bq1, Wk1, bk1, Wv1, bv1, Ws1, bs1);
    k_agg<<<(NN + 7) / 8, 256>>>(ea, We1, 0);          // -> hA

    // global add pool
    k_pool<<<(int)(((long long)NN * CC + 255) / 256), 256>>>(batch, 0);

    // MLP head
    k_mlp1<<<(GG * L0 + 255) / 256, 256>>>(Wl0, bl0);
    k_mlp2<<<(GG * L1 + 255) / 256, 256>>>(Wl1, bl1);
    k_mlp3<<<1, 256>>>(Wl2, bl2, out);
}

// round 7
// speedup vs baseline: 1.2162x; 1.1493x over previous
#include <cuda_runtime.h>
#include <math_constants.h>

#define NN 50000
#define EE 800000
#define CC 128
#define GG 128
#define L0 512
#define L1 256

// ---------------- scratch (static device globals; no allocation) ----------------
__device__ float  g_qkvs[(size_t)NN * 512];   // q|k|v|skip per node
__device__ float  g_hA[(size_t)NN * CC];
__device__ float  g_hB[(size_t)NN * CC];
__device__ int    g_cnt[NN];
__device__ int    g_off[NN + 1];
__device__ int    g_cur[NN];
__device__ int    g_srcA[EE];
__device__ float4 g_eaC[EE];                  // edge_attr in CSR order (w unused)
__device__ int    g_gstart[GG + 1];
__device__ float  g_pool[GG * CC];
__device__ float  g_m1[GG * L0];
__device__ float  g_m2[GG * L1];

// ---------------- packed f32x2 helpers ----------------
__device__ __forceinline__ unsigned long long rep2(float x) {
    unsigned long long r;
    asm("mov.b64 %0, {%1, %1};" : "=l"(r) : "f"(x));
    return r;
}
#define FFMA_X2(acc, a, b) asm("fma.rn.f32x2 %0, %1, %2, %0;" : "+l"(acc) : "l"(a), "l"(b))

union U64F2 { unsigned long long u; float2 f; };

// ---------------- CSR build ----------------
__global__ void k_zero() {
    int i = blockIdx.x * blockDim.x + threadIdx.x;
    if (i < NN) g_cnt[i] = 0;
}

// gstart[g] = lower_bound(batch, g)  (batch is sorted); no atomics, no races
__global__ void k_gstart(const int* __restrict__ batch) {
    int g = threadIdx.x;
    if (g > GG) return;
    int lo = 0, hi = NN;
    while (lo < hi) {
        int mid = (lo + hi) >> 1;
        if (batch[mid] < g) lo = mid + 1; else hi = mid;
    }
    g_gstart[g] = lo;
}

__global__ void k_count(const int* __restrict__ ei) {
    int e = blockIdx.x * blockDim.x + threadIdx.x;
    if (e < EE) atomicAdd(&g_cnt[ei[EE + e]], 1);
}

// single-block exclusive scan of g_cnt -> g_off (+ copy to g_cur)
__global__ void k_scan() {
    const int T = 1024;
    const int CHUNK = (NN + T - 1) / T;   // 49
    int t = threadIdx.x;
    int base = t * CHUNK;
    int s = 0;
    for (int j = 0; j < CHUNK; j++) {
        int idx = base + j;
        if (idx < NN) s += g_cnt[idx];
    }
    __shared__ int sh[T];
    sh[t] = s;
    __syncthreads();
    for (int d = 1; d < T; d <<= 1) {
        int v = (t >= d) ? sh[t - d] : 0;
        __syncthreads();
        sh[t] += v;
        __syncthreads();
    }
    int run = sh[t] - s;  // exclusive prefix of this chunk
    for (int j = 0; j < CHUNK; j++) {
        int idx = base + j;
        if (idx < NN) {
            g_off[idx] = run;
            g_cur[idx] = run;
            run += g_cnt[idx];
        }
    }
    if (t == T - 1) g_off[NN] = sh[T - 1];
}

__global__ void k_fill(const int* __restrict__ ei, const float* __restrict__ ea) {
    int e = blockIdx.x * blockDim.x + threadIdx.x;
    if (e < EE) {
        int d = ei[EE + e];
        int p = atomicAdd(&g_cur[d], 1);
        g_srcA[p] = ei[e];
        float4 v;
        v.x = ea[e * 3 + 0]; v.y = ea[e * 3 + 1]; v.z = ea[e * 3 + 2]; v.w = 0.f;
        g_eaC[p] = v;
    }
}

// ---------------- layer-0 projection (din = 4) ----------------
__global__ void k_gemm0(const float* __restrict__ x,
                        const float* __restrict__ Wq, const float* __restrict__ bq,
                        const float* __restrict__ Wk, const float* __restrict__ bk,
                        const float* __restrict__ Wv, const float* __restrict__ bv,
                        const float* __restrict__ Ws, const float* __restrict__ bs) {
    long long idx = (long long)blockIdx.x * blockDim.x + threadIdx.x;
    if (idx >= (long long)NN * 512) return;
    int n = (int)(idx >> 9);
    int col = (int)(idx & 511);
    int grp = col >> 7;
    int c = col & 127;
    const float* W; const float* b;
    if      (grp == 0) { W = Wq; b = bq; }
    else if (grp == 1) { W = Wk; b = bk; }
    else if (grp == 2) { W = Wv; b = bv; }
    else               { W = Ws; b = bs; }
    float x0 = x[n * 4 + 0], x1 = x[n * 4 + 1], x2 = x[n * 4 + 2], x3 = x[n * 4 + 3];
    float v = b[c] + x0 * W[c] + x1 * W[128 + c] + x2 * W[256 + c] + x3 * W[384 + c];
    g_qkvs[(size_t)n * 512 + col] = v;
}

// ---------------- main projection GEMM: [NN,128] @ [128,128] x4 groups ----------------
// 128x128 tile, 512 threads, 8x4 microtile, BK=16, packed f32x2 FMA (M-pairs)
#define AS_STRIDE 132
__global__ __launch_bounds__(512) void k_gemm(int inSel,
                        const float* __restrict__ Wq, const float* __restrict__ bq,
                        const float* __restrict__ Wk, const float* __restrict__ bk,
                        const float* __restrict__ Wv, const float* __restrict__ bv,
                        const float* __restrict__ Ws, const float* __restrict__ bs) {
    const float* __restrict__ H = inSel ? g_hB : g_hA;
    __shared__ __align__(16) float As[16 * AS_STRIDE];  // [k][m], m=0..127
    __shared__ __align__(16) float Bs[16 * 128];        // [k][n], n=0..127

    int tid = threadIdx.x;
    int tx = tid & 31;          // 32 col groups of 4
    int ty = tid >> 5;          // 16 row groups of 8 (warp-uniform!)
    int row0 = blockIdx.y * 128;
    int grp = blockIdx.x;       // 0..3 : q,k,v,s
    const float* W; const float* b;
    if      (grp == 0) { W = Wq; b = bq; }
    else if (grp == 1) { W = Wk; b = bk; }
    else if (grp == 2) { W = Wv; b = bv; }
    else               { W = Ws; b = bs; }

    unsigned long long acc[4][4];   // [row-pair][col]; lo=row ty*8+2rp, hi=+1
#pragma unroll
    for (int i = 0; i < 4; i++)
#pragma unroll
        for (int j = 0; j < 4; j++) acc[i][j] = 0ULL;

    int am = tid >> 2;            // 0..127 row within tile
    int ak = (tid & 3) * 4;       // k offset (float4)
    int bkL = tid >> 5;           // 0..15
    int bnL = (tid & 31) * 4;     // 0..124

    for (int kk = 0; kk < 128; kk += 16) {
        // A tile transposed into As[k][m]
        float4 a4;
        if (row0 + am < NN)
            a4 = *(const float4*)&H[(size_t)(row0 + am) * 128 + kk + ak];
        else
            a4 = make_float4(0.f, 0.f, 0.f, 0.f);
        As[(ak + 0) * AS_STRIDE + am] = a4.x;
        As[(ak + 1) * AS_STRIDE + am] = a4.y;
        As[(ak + 2) * AS_STRIDE + am] = a4.z;
        As[(ak + 3) * AS_STRIDE + am] = a4.w;
        // B tile: 16 k x 128 n
        *(float4*)&Bs[bkL * 128 + bnL] = *(const float4*)&W[(size_t)(kk + bkL) * 128 + bnL];
        __syncthreads();
#pragma unroll
        for (int k = 0; k < 16; k++) {
            ulonglong2 a01 = *(const ulonglong2*)&As[k * AS_STRIDE + ty * 8];
            ulonglong2 a23 = *(const ulonglong2*)&As[k * AS_STRIDE + ty * 8 + 4];
            float4 b4 = *(const float4*)&Bs[k * 128 + tx * 4];
            unsigned long long ap[4] = {a01.x, a01.y, a23.x, a23.y};
            unsigned long long br[4] = {rep2(b4.x), rep2(b4.y), rep2(b4.z), rep2(b4.w)};
#pragma unroll
            for (int ip = 0; ip < 4; ip++)
#pragma unroll
                for (int j = 0; j < 4; j++) FFMA_X2(acc[ip][j], ap[ip], br[j]);
        }
        __syncthreads();
    }

    int outcolbase = grp * 128 + tx * 4;
    float4 bias = *(const float4*)&b[tx * 4];
    float bb[4] = {bias.x, bias.y, bias.z, bias.w};
#pragma unroll
    for (int ip = 0; ip < 4; ip++) {
        U64F2 c0, c1, c2, c3;
        c0.u = acc[ip][0]; c1.u = acc[ip][1]; c2.u = acc[ip][2]; c3.u = acc[ip][3];
        int rlo = row0 + ty * 8 + 2 * ip;
        if (rlo < NN) {
            float4 o;
            o.x = c0.f.x + bb[0]; o.y = c1.f.x + bb[1];
            o.z = c2.f.x + bb[2]; o.w = c3.f.x + bb[3];
            *(float4*)&g_qkvs[(size_t)rlo * 512 + outcolbase] = o;
        }
        int rhi = rlo + 1;
        if (rhi < NN) {
            float4 o;
            o.x = c0.f.y + bb[0]; o.y = c1.f.y + bb[1];
            o.z = c2.f.y + bb[2]; o.w = c3.f.y + bb[3];
            *(float4*)&g_qkvs[(size_t)rhi * 512 + outcolbase] = o;
        }
    }
}

// ---------------- edge aggregation: warp per dst node, online softmax ----------------
// Uses e = We.ea factorization: logit = (q.k + ea.t)/sqrt(C), t = We.q per node;
// out = sum(a*v) + We^T(sum(a*ea)).
__global__ __launch_bounds__(256) void k_agg(const float* __restrict__ We,
                                             int outSel) {
    __shared__ float sWe[384];
    for (int i = threadIdx.x; i < 384; i += 256) sWe[i] = We[i];
    __syncthreads();

    int node = blockIdx.x * 8 + (threadIdx.x >> 5);
    if (node >= NN) return;
    int lane = threadIdx.x & 31;

    const float4* __restrict__ q4 = (const float4*)&g_qkvs[(size_t)node * 512];
    float4 qv = q4[lane];                 // cols lane*4 .. lane*4+3

    // t = We . q  (3 scalars, warp-reduced)
    float t0, t1, t2;
    {
        int c = lane * 4;
        t0 = sWe[c] * qv.x + sWe[c + 1] * qv.y + sWe[c + 2] * qv.z + sWe[c + 3] * qv.w;
        c += 128;
        t1 = sWe[c] * qv.x + sWe[c + 1] * qv.y + sWe[c + 2] * qv.z + sWe[c + 3] * qv.w;
        c += 128;
        t2 = sWe[c] * qv.x + sWe[c + 1] * qv.y + sWe[c + 2] * qv.z + sWe[c + 3] * qv.w;
#pragma unroll
        for (int o = 16; o > 0; o >>= 1) {
            t0 += __shfl_xor_sync(0xffffffffu, t0, o);
            t1 += __shfl_xor_sync(0xffffffffu, t1, o);
            t2 += __shfl_xor_sync(0xffffffffu, t2, o);
        }
    }

    float m = -CUDART_INF_F, den = 0.f;
    float4 acc = make_float4(0.f, 0.f, 0.f, 0.f);
    float s0 = 0.f, s1 = 0.f, s2 = 0.f;      // sum w*ea
    const float scale = 0.08838834764831845f; // 1/sqrt(128)

    int beg = __ldg(&g_off[node]), end = __ldg(&g_off[node + 1]);
    int p = beg;
    for (; p + 2 <= end; p += 2) {
        int n0 = __ldg(&g_srcA[p]), n1 = __ldg(&g_srcA[p + 1]);
        float4 ea0 = g_eaC[p], ea1 = g_eaC[p + 1];
        const float4* __restrict__ r0 = (const float4*)&g_qkvs[(size_t)n0 * 512 + 128];
        const float4* __restrict__ r1 = (const float4*)&g_qkvs[(size_t)n1 * 512 + 128];
        float4 kv0 = r0[lane], vv0 = r0[lane + 32];
        float4 kv1 = r1[lane], vv1 = r1[lane + 32];
        float d0 = qv.x * kv0.x + qv.y * kv0.y + qv.z * kv0.z + qv.w * kv0.w;
        float d1 = qv.x * kv1.x + qv.y * kv1.y + qv.z * kv1.z + qv.w * kv1.w;
#pragma unroll
        for (int o = 16; o > 0; o >>= 1) {
            d0 += __shfl_xor_sync(0xffffffffu, d0, o);
            d1 += __shfl_xor_sync(0xffffffffu, d1, o);
        }
        float l0 = (d0 + ea0.x * t0 + ea0.y * t1 + ea0.z * t2) * scale;
        float l1 = (d1 + ea1.x * t0 + ea1.y * t1 + ea1.z * t2) * scale;
        float nm = fmaxf(m, fmaxf(l0, l1));
        float corr = __expf(m - nm);
        float w0 = __expf(l0 - nm);
        float w1 = __expf(l1 - nm);
        den = den * corr + w0 + w1;
        acc.x = acc.x * corr + w0 * vv0.x + w1 * vv1.x;
        acc.y = acc.y * corr + w0 * vv0.y + w1 * vv1.y;
        acc.z = acc.z * corr + w0 * vv0.z + w1 * vv1.z;
        acc.w = acc.w * corr + w0 * vv0.w + w1 * vv1.w;
        s0 = s0 * corr + w0 * ea0.x + w1 * ea1.x;
        s1 = s1 * corr + w0 * ea0.y + w1 * ea1.y;
        s2 = s2 * corr + w0 * ea0.z + w1 * ea1.z;
        m = nm;
    }
    if (p < end) {
        int n0 = __ldg(&g_srcA[p]);
        float4 ea0 = g_eaC[p];
        const float4* __restrict__ r0 = (const float4*)&g_qkvs[(size_t)n0 * 512 + 128];
        float4 kv0 = r0[lane], vv0 = r0[lane + 32];
        float d0 = qv.x * kv0.x + qv.y * kv0.y + qv.z * kv0.z + qv.w * kv0.w;
#pragma unroll
        for (int o = 16; o > 0; o >>= 1) d0 += __shfl_xor_sync(0xffffffffu, d0, o);
        float l0 = (d0 + ea0.x * t0 + ea0.y * t1 + ea0.z * t2) * scale;
        float nm = fmaxf(m, l0);
        float corr = __expf(m - nm);
        float w0 = __expf(l0 - nm);
        den = den * corr + w0;
        acc.x = acc.x * corr + w0 * vv0.x;
        acc.y = acc.y * corr + w0 * vv0.y;
        acc.z = acc.z * corr + w0 * vv0.z;
        acc.w = acc.w * corr + w0 * vv0.w;
        s0 = s0 * corr + w0 * ea0.x;
        s1 = s1 * corr + w0 * ea0.y;
        s2 = s2 * corr + w0 * ea0.z;
        m = nm;
    }

    float inv = den > 0.f ? 1.f / den : 0.f;
    s0 *= inv; s1 *= inv; s2 *= inv;
    float4 skip = q4[96 + lane];           // cols 384.. of qkvs row
    int c = lane * 4;
    float4 o;
    o.x = acc.x * inv + s0 * sWe[c + 0] + s1 * sWe[128 + c + 0] + s2 * sWe[256 + c + 0] + skip.x;
    o.y = acc.y * inv + s0 * sWe[c + 1] + s1 * sWe[128 + c + 1] + s2 * sWe[256 + c + 1] + skip.y;
    o.z = acc.z * inv + s0 * sWe[c + 2] + s1 * sWe[128 + c + 2] + s2 * sWe[256 + c + 2] + skip.z;
    o.w = acc.w * inv + s0 * sWe[c + 3] + s1 * sWe[128 + c + 3] + s2 * sWe[256 + c + 3] + skip.w;
    o.x = o.x > 0.f ? o.x : 0.01f * o.x;
    o.y = o.y > 0.f ? o.y : 0.01f * o.y;
    o.z = o.z > 0.f ? o.z : 0.01f * o.z;
    o.w = o.w > 0.f ? o.w : 0.01f * o.w;
    float* __restrict__ out = outSel ? g_hB : g_hA;
    *(float4*)&out[(size_t)node * CC + c] = o;
}

// ---------------- pooling: batch is sorted -> segmented sum, no atomics ----------------
__global__ void k_pool(int hSel) {
    int g = blockIdx.x;       // graph
    int c = threadIdx.x;      // channel
    const float* h = hSel ? g_hB : g_hA;
    int s = g_gstart[g], e = g_gstart[g + 1];
    float acc = 0.f;
    for (int n = s; n < e; n++) acc += h[(size_t)n * CC + c];
    g_pool[g * CC + c] = acc;
}

// ---------------- MLP head ----------------
__global__ void k_mlp1(const float* __restrict__ W, const float* __restrict__ b) {
    int idx = blockIdx.x * blockDim.x + threadIdx.x;
    if (idx >= GG * L0) return;
    int r = idx >> 9, c = idx & (L0 - 1);
    float s = b[c];
    for (int k = 0; k < CC; k++) s += g_pool[r * CC + k] * W[k * L0 + c];
    g_m1[idx] = s > 0.f ? s : 0.f;
}

__global__ void k_mlp2(const float* __restrict__ W, const float* __restrict__ b) {
    int idx = blockIdx.x * blockDim.x + threadIdx.x;
    if (idx >= GG * L1) return;
    int r = idx >> 8, c = idx & (L1 - 1);
    float s = b[c];
    for (int k = 0; k < L0; k++) s += g_m1[r * L0 + k] * W[k * L1 + c];
    g_m2[idx] = s > 0.f ? s : 0.f;
}

__global__ void k_mlp3(const float* __restrict__ W, const float* __restrict__ b,
                       float* __restrict__ out) {
    int idx = threadIdx.x;
    if (idx >= GG * 2) return;
    int r = idx >> 1, c = idx & 1;
    float s = b[c];
    for (int k = 0; k < L1; k++) s += g_m2[r * L1 + k] * W[k * 2 + c];
    out[idx] = s;
}

// ---------------- launch ----------------
extern "C" void kernel_launch(void* const* d_in, const int* in_sizes, int n_in,
                              void* d_out, int out_size) {
    const float* x     = (const float*)d_in[0];
    const int*   ei    = (const int*)d_in[1];
    const float* ea    = (const float*)d_in[2];
    const int*   batch = (const int*)d_in[3];
    const float* Wq0 = (const float*)d_in[4];  const float* bq0 = (const float*)d_in[5];
    const float* Wk0 = (const float*)d_in[6];  const float* bk0 = (const float*)d_in[7];
    const float* Wv0 = (const float*)d_in[8];  const float* bv0 = (const float*)d_in[9];
    const float* We0 = (const float*)d_in[10];
    const float* Ws0 = (const float*)d_in[11]; const float* bs0 = (const float*)d_in[12];
    const float* Wq1 = (const float*)d_in[13]; const float* bq1 = (const float*)d_in[14];
    const float* Wk1 = (const float*)d_in[15]; const float* bk1 = (const float*)d_in[16];
    const float* Wv1 = (const float*)d_in[17]; const float* bv1 = (const float*)d_in[18];
    const float* We1 = (const float*)d_in[19];
    const float* Ws1 = (const float*)d_in[20]; const float* bs1 = (const float*)d_in[21];
    const float* Wl0 = (const float*)d_in[22]; const float* bl0 = (const float*)d_in[23];
    const float* Wl1 = (const float*)d_in[24]; const float* bl1 = (const float*)d_in[25];
    const float* Wl2 = (const float*)d_in[26]; const float* bl2 = (const float*)d_in[27];
    float* out = (float*)d_out;

    // CSR build (by dst) + graph starts (binary search on sorted batch)
    k_zero<<<(NN + 255) / 256, 256>>>();
    k_gstart<<<1, GG + 1>>>(batch);
    k_count<<<(EE + 255) / 256, 256>>>(ei);
    k_scan<<<1, 1024>>>();
    k_fill<<<(EE + 255) / 256, 256>>>(ei, ea);

    dim3 gemmGrid(4, (NN + 127) / 128);

    // layer 0
    k_gemm0<<<(int)(((long long)NN * 512 + 255) / 256), 256>>>(x, Wq0, bq0, Wk0, bk0, Wv0, bv0, Ws0, bs0);
    k_agg<<<(NN + 7) / 8, 256>>>(We0, 0);              // -> hA
    // layer 1 (shared weights)
    k_gemm<<<gemmGrid, 512>>>(0, Wq1, bq1, Wk1, bk1, Wv1, bv1, Ws1, bs1);
    k_agg<<<(NN + 7) / 8, 256>>>(We1, 1);              // -> hB
    // layer 2 (same weights)
    k_gemm<<<gemmGrid, 512>>>(1, Wq1, bq1, Wk1, bk1, Wv1, bv1, Ws1, bs1);
    k_agg<<<(NN + 7) / 8, 256>>>(We1, 0);              // -> hA

    // global add pool (segmented, batch sorted)
    k_pool<<<GG, CC>>>(0);

    // MLP head
    k_mlp1<<<(GG * L0 + 255) / 256, 256>>>(Wl0, bl0);
    k_mlp2<<<(GG * L1 + 255) / 256, 256>>>(Wl1, bl1);
    k_mlp3<<<1, 256>>>(Wl2, bl2, out);
}

// round 8
// speedup vs baseline: 1.3156x; 1.0818x over previous
#include <cuda_runtime.h>
#include <math_constants.h>

#define NN 50000
#define EE 800000
#define CC 128
#define GG 128
#define L0 512
#define L1 256

#define N4 (NN / 4)                 // 12500 int4 elements (NN divisible by 4)
#define SCAN_BLK 256
#define SCAN_NBLK ((N4 + SCAN_BLK - 1) / SCAN_BLK)   // 49

// ---------------- scratch (static device globals; no allocation) ----------------
__device__ float  g_qkvs[(size_t)NN * 512];   // q|k|v|skip per node
__device__ float  g_hA[(size_t)NN * CC];
__device__ float  g_hB[(size_t)NN * CC];
__device__ int    g_cnt[NN];
__device__ int    g_off[NN + 4];              // padded for int4 store
__device__ int    g_cur[NN + 4];
__device__ int    g_bsum[SCAN_NBLK];
__device__ int    g_boff[SCAN_NBLK];
__device__ int    g_srcA[EE];
__device__ float4 g_eaC[EE];                  // edge_attr in CSR order (w unused)
__device__ int    g_gstart[GG + 1];
__device__ float  g_pool[GG * CC];
__device__ float  g_m1[GG * L0];
__device__ float  g_m2[GG * L1];

// ---------------- packed f32x2 helpers ----------------
__device__ __forceinline__ unsigned long long rep2(float x) {
    unsigned long long r;
    asm("mov.b64 %0, {%1, %1};" : "=l"(r) : "f"(x));
    return r;
}
#define FFMA_X2(acc, a, b) asm("fma.rn.f32x2 %0, %1, %2, %0;" : "+l"(acc) : "l"(a), "l"(b))

union U64F2 { unsigned long long u; float2 f; };

// ---------------- CSR build ----------------
// zero cnt + gstart via binary search on sorted batch (no atomics, no races)
__global__ void k_zero(const int* __restrict__ batch) {
    int i = blockIdx.x * blockDim.x + threadIdx.x;
    if (i < NN) g_cnt[i] = 0;
    if (i <= GG) {
        int lo = 0, hi = NN;
        while (lo < hi) {
            int mid = (lo + hi) >> 1;
            if (batch[mid] < i) lo = mid + 1; else hi = mid;
        }
        g_gstart[i] = lo;
    }
}

__global__ void k_count(const int* __restrict__ ei) {
    int e = blockIdx.x * blockDim.x + threadIdx.x;
    if (e < EE) atomicAdd(&g_cnt[ei[EE + e]], 1);
}

// ---- 3-kernel coalesced scan of g_cnt -> g_off/g_cur ----
__global__ void k_sum() {
    __shared__ int sh[SCAN_BLK];
    int t = threadIdx.x;
    int i4 = blockIdx.x * SCAN_BLK + t;
    int s = 0;
    if (i4 < N4) {
        int4 c = *(const int4*)&g_cnt[i4 * 4];
        s = c.x + c.y + c.z + c.w;
    }
    sh[t] = s;
    __syncthreads();
    for (int d = SCAN_BLK / 2; d > 0; d >>= 1) {
        if (t < d) sh[t] += sh[t + d];
        __syncthreads();
    }
    if (t == 0) g_bsum[blockIdx.x] = sh[0];
}

__global__ void k_bscan() {
    __shared__ int sh[64];
    int t = threadIdx.x;
    int v = (t < SCAN_NBLK) ? g_bsum[t] : 0;
    sh[t] = v;
    __syncthreads();
    for (int d = 1; d < 64; d <<= 1) {
        int u = (t >= d) ? sh[t - d] : 0;
        __syncthreads();
        sh[t] += u;
        __syncthreads();
    }
    if (t < SCAN_NBLK) g_boff[t] = sh[t] - v;   // exclusive
    if (t == 63) g_off[NN] = sh[63];            // total
}

__global__ void k_scat() {
    __shared__ int sh[SCAN_BLK];
    int t = threadIdx.x;
    int i4 = blockIdx.x * SCAN_BLK + t;
    int4 c = make_int4(0, 0, 0, 0);
    if (i4 < N4) c = *(const int4*)&g_cnt[i4 * 4];
    int s = c.x + c.y + c.z + c.w;
    sh[t] = s;
    __syncthreads();
    for (int d = 1; d < SCAN_BLK; d <<= 1) {
        int u = (t >= d) ? sh[t - d] : 0;
        __syncthreads();
        sh[t] += u;
        __syncthreads();
    }
    if (i4 < N4) {
        int base = g_boff[blockIdx.x] + sh[t] - s;   // exclusive prefix
        int4 o;
        o.x = base;
        o.y = base + c.x;
        o.z = o.y + c.y;
        o.w = o.z + c.z;
        *(int4*)&g_off[i4 * 4] = o;
        *(int4*)&g_cur[i4 * 4] = o;
    }
}

__global__ void k_fill(const int* __restrict__ ei, const float* __restrict__ ea) {
    int e = blockIdx.x * blockDim.x + threadIdx.x;
    if (e < EE) {
        int d = ei[EE + e];
        int p = atomicAdd(&g_cur[d], 1);
        g_srcA[p] = ei[e];
        float4 v;
        v.x = ea[e * 3 + 0]; v.y = ea[e * 3 + 1]; v.z = ea[e * 3 + 2]; v.w = 0.f;
        g_eaC[p] = v;
    }
}

// ---------------- layer-0 projection (din = 4) ----------------
__global__ void k_gemm0(const float* __restrict__ x,
                        const float* __restrict__ Wq, const float* __restrict__ bq,
                        const float* __restrict__ Wk, const float* __restrict__ bk,
                        const float* __restrict__ Wv, const float* __restrict__ bv,
                        const float* __restrict__ Ws, const float* __restrict__ bs) {
    long long idx = (long long)blockIdx.x * blockDim.x + threadIdx.x;
    if (idx >= (long long)NN * 512) return;
    int n = (int)(idx >> 9);
    int col = (int)(idx & 511);
    int grp = col >> 7;
    int c = col & 127;
    const float* W; const float* b;
    if      (grp == 0) { W = Wq; b = bq; }
    else if (grp == 1) { W = Wk; b = bk; }
    else if (grp == 2) { W = Wv; b = bv; }
    else               { W = Ws; b = bs; }
    float x0 = x[n * 4 + 0], x1 = x[n * 4 + 1], x2 = x[n * 4 + 2], x3 = x[n * 4 + 3];
    float v = b[c] + x0 * W[c] + x1 * W[128 + c] + x2 * W[256 + c] + x3 * W[384 + c];
    g_qkvs[(size_t)n * 512 + col] = v;
}

// ---------------- main projection GEMM: [NN,128] @ [128,128] x4 groups ----------------
// 128x128 tile, 512 threads, 8x4 microtile, BK=16, packed f32x2 FMA (M-pairs)
#define AS_STRIDE 132
__global__ __launch_bounds__(512) void k_gemm(int inSel,
                        const float* __restrict__ Wq, const float* __restrict__ bq,
                        const float* __restrict__ Wk, const float* __restrict__ bk,
                        const float* __restrict__ Wv, const float* __restrict__ bv,
                        const float* __restrict__ Ws, const float* __restrict__ bs) {
    const float* __restrict__ H = inSel ? g_hB : g_hA;
    __shared__ __align__(16) float As[16 * AS_STRIDE];  // [k][m], m=0..127
    __shared__ __align__(16) float Bs[16 * 128];        // [k][n], n=0..127

    int tid = threadIdx.x;
    int tx = tid & 31;          // 32 col groups of 4
    int ty = tid >> 5;          // 16 row groups of 8 (warp-uniform!)
    int row0 = blockIdx.y * 128;
    int grp = blockIdx.x;       // 0..3 : q,k,v,s
    const float* W; const float* b;
    if      (grp == 0) { W = Wq; b = bq; }
    else if (grp == 1) { W = Wk; b = bk; }
    else if (grp == 2) { W = Wv; b = bv; }
    else               { W = Ws; b = bs; }

    unsigned long long acc[4][4];   // [row-pair][col]; lo=row ty*8+2rp, hi=+1
#pragma unroll
    for (int i = 0; i < 4; i++)
#pragma unroll
        for (int j = 0; j < 4; j++) acc[i][j] = 0ULL;

    int am = tid >> 2;            // 0..127 row within tile
    int ak = (tid & 3) * 4;       // k offset (float4)
    int bkL = tid >> 5;           // 0..15
    int bnL = (tid & 31) * 4;     // 0..124

    for (int kk = 0; kk < 128; kk += 16) {
        // A tile transposed into As[k][m]
        float4 a4;
        if (row0 + am < NN)
            a4 = *(const float4*)&H[(size_t)(row0 + am) * 128 + kk + ak];
        else
            a4 = make_float4(0.f, 0.f, 0.f, 0.f);
        As[(ak + 0) * AS_STRIDE + am] = a4.x;
        As[(ak + 1) * AS_STRIDE + am] = a4.y;
        As[(ak + 2) * AS_STRIDE + am] = a4.z;
        As[(ak + 3) * AS_STRIDE + am] = a4.w;
        // B tile: 16 k x 128 n
        *(float4*)&Bs[bkL * 128 + bnL] = *(const float4*)&W[(size_t)(kk + bkL) * 128 + bnL];
        __syncthreads();
#pragma unroll
        for (int k = 0; k < 16; k++) {
            ulonglong2 a01 = *(const ulonglong2*)&As[k * AS_STRIDE + ty * 8];
            ulonglong2 a23 = *(const ulonglong2*)&As[k * AS_STRIDE + ty * 8 + 4];
            float4 b4 = *(const float4*)&Bs[k * 128 + tx * 4];
            unsigned long long ap[4] = {a01.x, a01.y, a23.x, a23.y};
            unsigned long long br[4] = {rep2(b4.x), rep2(b4.y), rep2(b4.z), rep2(b4.w)};
#pragma unroll
            for (int ip = 0; ip < 4; ip++)
#pragma unroll
                for (int j = 0; j < 4; j++) FFMA_X2(acc[ip][j], ap[ip], br[j]);
        }
        __syncthreads();
    }

    int outcolbase = grp * 128 + tx * 4;
    float4 bias = *(const float4*)&b[tx * 4];
    float bb[4] = {bias.x, bias.y, bias.z, bias.w};
#pragma unroll
    for (int ip = 0; ip < 4; ip++) {
        U64F2 c0, c1, c2, c3;
        c0.u = acc[ip][0]; c1.u = acc[ip][1]; c2.u = acc[ip][2]; c3.u = acc[ip][3];
        int rlo = row0 + ty * 8 + 2 * ip;
        if (rlo < NN) {
            float4 o;
            o.x = c0.f.x + bb[0]; o.y = c1.f.x + bb[1];
            o.z = c2.f.x + bb[2]; o.w = c3.f.x + bb[3];
            *(float4*)&g_qkvs[(size_t)rlo * 512 + outcolbase] = o;
        }
        int rhi = rlo + 1;
        if (rhi < NN) {
            float4 o;
            o.x = c0.f.y + bb[0]; o.y = c1.f.y + bb[1];
            o.z = c2.f.y + bb[2]; o.w = c3.f.y + bb[3];
            *(float4*)&g_qkvs[(size_t)rhi * 512 + outcolbase] = o;
        }
    }
}

// ---------------- edge aggregation: warp per dst node, online softmax ----------------
// Uses e = We.ea factorization: logit = (q.k + ea.t)/sqrt(C), t = We.q per node;
// out = sum(a*v) + We^T(sum(a*ea)).
__global__ __launch_bounds__(256) void k_agg(const float* __restrict__ We,
                                             int outSel) {
    __shared__ float sWe[384];
    for (int i = threadIdx.x; i < 384; i += 256) sWe[i] = We[i];
    __syncthreads();

    int node = blockIdx.x * 8 + (threadIdx.x >> 5);
    if (node >= NN) return;
    int lane = threadIdx.x & 31;

    const float4* __restrict__ q4 = (const float4*)&g_qkvs[(size_t)node * 512];
    float4 qv = q4[lane];                 // cols lane*4 .. lane*4+3

    // t = We . q  (3 scalars, warp-reduced)
    float t0, t1, t2;
    {
        int c = lane * 4;
        t0 = sWe[c] * qv.x + sWe[c + 1] * qv.y + sWe[c + 2] * qv.z + sWe[c + 3] * qv.w;
        c += 128;
        t1 = sWe[c] * qv.x + sWe[c + 1] * qv.y + sWe[c + 2] * qv.z + sWe[c + 3] * qv.w;
        c += 128;
        t2 = sWe[c] * qv.x + sWe[c + 1] * qv.y + sWe[c + 2] * qv.z + sWe[c + 3] * qv.w;
#pragma unroll
        for (int o = 16; o > 0; o >>= 1) {
            t0 += __shfl_xor_sync(0xffffffffu, t0, o);
            t1 += __shfl_xor_sync(0xffffffffu, t1, o);
            t2 += __shfl_xor_sync(0xffffffffu, t2, o);
        }
    }

    float m = -CUDART_INF_F, den = 0.f;
    float4 acc = make_float4(0.f, 0.f, 0.f, 0.f);
    float s0 = 0.f, s1 = 0.f, s2 = 0.f;      // sum w*ea
    const float scale = 0.08838834764831845f; // 1/sqrt(128)

    int beg = __ldg(&g_off[node]), end = __ldg(&g_off[node + 1]);
    int p = beg;
    for (; p + 2 <= end; p += 2) {
        int n0 = __ldg(&g_srcA[p]), n1 = __ldg(&g_srcA[p + 1]);
        float4 ea0 = g_eaC[p], ea1 = g_eaC[p + 1];
        const float4* __restrict__ r0 = (const float4*)&g_qkvs[(size_t)n0 * 512 + 128];
        const float4* __restrict__ r1 = (const float4*)&g_qkvs[(size_t)n1 * 512 + 128];
        float4 kv0 = r0[lane], vv0 = r0[lane + 32];
        float4 kv1 = r1[lane], vv1 = r1[lane + 32];
        float d0 = qv.x * kv0.x + qv.y * kv0.y + qv.z * kv0.z + qv.w * kv0.w;
        float d1 = qv.x * kv1.x + qv.y * kv1.y + qv.z * kv1.z + qv.w * kv1.w;
#pragma unroll
        for (int o = 16; o > 0; o >>= 1) {
            d0 += __shfl_xor_sync(0xffffffffu, d0, o);
            d1 += __shfl_xor_sync(0xffffffffu, d1, o);
        }
        float l0 = (d0 + ea0.x * t0 + ea0.y * t1 + ea0.z * t2) * scale;
        float l1 = (d1 + ea1.x * t0 + ea1.y * t1 + ea1.z * t2) * scale;
        float nm = fmaxf(m, fmaxf(l0, l1));
        float corr = __expf(m - nm);
        float w0 = __expf(l0 - nm);
        float w1 = __expf(l1 - nm);
        den = den * corr + w0 + w1;
        acc.x = acc.x * corr + w0 * vv0.x + w1 * vv1.x;
        acc.y = acc.y * corr + w0 * vv0.y + w1 * vv1.y;
        acc.z = acc.z * corr + w0 * vv0.z + w1 * vv1.z;
        acc.w = acc.w * corr + w0 * vv0.w + w1 * vv1.w;
        s0 = s0 * corr + w0 * ea0.x + w1 * ea1.x;
        s1 = s1 * corr + w0 * ea0.y + w1 * ea1.y;
        s2 = s2 * corr + w0 * ea0.z + w1 * ea1.z;
        m = nm;
    }
    if (p < end) {
        int n0 = __ldg(&g_srcA[p]);
        float4 ea0 = g_eaC[p];
        const float4* __restrict__ r0 = (const float4*)&g_qkvs[(size_t)n0 * 512 + 128];
        float4 kv0 = r0[lane], vv0 = r0[lane + 32];
        float d0 = qv.x * kv0.x + qv.y * kv0.y + qv.z * kv0.z + qv.w * kv0.w;
#pragma unroll
        for (int o = 16; o > 0; o >>= 1) d0 += __shfl_xor_sync(0xffffffffu, d0, o);
        float l0 = (d0 + ea0.x * t0 + ea0.y * t1 + ea0.z * t2) * scale;
        float nm = fmaxf(m, l0);
        float corr = __expf(m - nm);
        float w0 = __expf(l0 - nm);
        den = den * corr + w0;
        acc.x = acc.x * corr + w0 * vv0.x;
        acc.y = acc.y * corr + w0 * vv0.y;
        acc.z = acc.z * corr + w0 * vv0.z;
        acc.w = acc.w * corr + w0 * vv0.w;
        s0 = s0 * corr + w0 * ea0.x;
        s1 = s1 * corr + w0 * ea0.y;
        s2 = s2 * corr + w0 * ea0.z;
        m = nm;
    }

    float inv = den > 0.f ? 1.f / den : 0.f;
    s0 *= inv; s1 *= inv; s2 *= inv;
    float4 skip = q4[96 + lane];           // cols 384.. of qkvs row
    int c = lane * 4;
    float4 o;
    o.x = acc.x * inv + s0 * sWe[c + 0] + s1 * sWe[128 + c + 0] + s2 * sWe[256 + c + 0] + skip.x;
    o.y = acc.y * inv + s0 * sWe[c + 1] + s1 * sWe[128 + c + 1] + s2 * sWe[256 + c + 1] + skip.y;
    o.z = acc.z * inv + s0 * sWe[c + 2] + s1 * sWe[128 + c + 2] + s2 * sWe[256 + c + 2] + skip.z;
    o.w = acc.w * inv + s0 * sWe[c + 3] + s1 * sWe[128 + c + 3] + s2 * sWe[256 + c + 3] + skip.w;
    o.x = o.x > 0.f ? o.x : 0.01f * o.x;
    o.y = o.y > 0.f ? o.y : 0.01f * o.y;
    o.z = o.z > 0.f ? o.z : 0.01f * o.z;
    o.w = o.w > 0.f ? o.w : 0.01f * o.w;
    float* __restrict__ out = outSel ? g_hB : g_hA;
    *(float4*)&out[(size_t)node * CC + c] = o;
}

// ---------------- pooling: batch is sorted -> segmented sum, no atomics ----------------
__global__ void k_pool(int hSel) {
    int g = blockIdx.x;       // graph
    int c = threadIdx.x;      // channel
    const float* h = hSel ? g_hB : g_hA;
    int s = g_gstart[g], e = g_gstart[g + 1];
    float acc = 0.f;
    for (int n = s; n < e; n++) acc += h[(size_t)n * CC + c];
    g_pool[g * CC + c] = acc;
}

// ---------------- MLP head ----------------
__global__ void k_mlp1(const float* __restrict__ W, const float* __restrict__ b) {
    int idx = blockIdx.x * blockDim.x + threadIdx.x;
    if (idx >= GG * L0) return;
    int r = idx >> 9, c = idx & (L0 - 1);
    float s = b[c];
    for (int k = 0; k < CC; k++) s += g_pool[r * CC + k] * W[k * L0 + c];
    g_m1[idx] = s > 0.f ? s : 0.f;
}

__global__ void k_mlp2(const float* __restrict__ W, const float* __restrict__ b) {
    int idx = blockIdx.x * blockDim.x + threadIdx.x;
    if (idx >= GG * L1) return;
    int r = idx >> 8, c = idx & (L1 - 1);
    float s = b[c];
    for (int k = 0; k < L0; k++) s += g_m1[r * L0 + k] * W[k * L1 + c];
    g_m2[idx] = s > 0.f ? s : 0.f;
}

__global__ void k_mlp3(const float* __restrict__ W, const float* __restrict__ b,
                       float* __restrict__ out) {
    int idx = threadIdx.x;
    if (idx >= GG * 2) return;
    int r = idx >> 1, c = idx & 1;
    float s = b[c];
    for (int k = 0; k < L1; k++) s += g_m2[r * L1 + k] * W[k * 2 + c];
    out[idx] = s;
}

// ---------------- launch ----------------
extern "C" void kernel_launch(void* const* d_in, const int* in_sizes, int n_in,
                              void* d_out, int out_size) {
    const float* x     = (const float*)d_in[0];
    const int*   ei    = (const int*)d_in[1];
    const float* ea    = (const float*)d_in[2];
    const int*   batch = (const int*)d_in[3];
    const float* Wq0 = (const float*)d_in[4];  const float* bq0 = (const float*)d_in[5];
    const float* Wk0 = (const float*)d_in[6];  const float* bk0 = (const float*)d_in[7];
    const float* Wv0 = (const float*)d_in[8];  const float* bv0 = (const float*)d_in[9];
    const float* We0 = (const float*)d_in[10];
    const float* Ws0 = (const float*)d_in[11]; const float* bs0 = (const float*)d_in[12];
    const float* Wq1 = (const float*)d_in[13]; const float* bq1 = (const float*)d_in[14];
    const float* Wk1 = (const float*)d_in[15]; const float* bk1 = (const float*)d_in[16];
    const float* Wv1 = (const float*)d_in[17]; const float* bv1 = (const float*)d_in[18];
    const float* We1 = (const float*)d_in[19];
    const float* Ws1 = (const float*)d_in[20]; const float* bs1 = (const float*)d_in[21];
    const float* Wl0 = (const float*)d_in[22]; const float* bl0 = (const float*)d_in[23];
    const float* Wl1 = (const float*)d_in[24]; const float* bl1 = (const float*)d_in[25];
    const float* Wl2 = (const float*)d_in[26]; const float* bl2 = (const float*)d_in[27];
    float* out = (float*)d_out;

    // CSR build (by dst) + graph starts
    k_zero<<<(NN + 255) / 256, 256>>>(batch);
    k_count<<<(EE + 255) / 256, 256>>>(ei);
    k_sum<<<SCAN_NBLK, SCAN_BLK>>>();
    k_bscan<<<1, 64>>>();
    k_scat<<<SCAN_NBLK, SCAN_BLK>>>();
    k_fill<<<(EE + 255) / 256, 256>>>(ei, ea);

    dim3 gemmGrid(4, (NN + 127) / 128);

    // layer 0
    k_gemm0<<<(int)(((long long)NN * 512 + 255) / 256), 256>>>(x, Wq0, bq0, Wk0, bk0, Wv0, bv0, Ws0, bs0);
    k_agg<<<(NN + 7) / 8, 256>>>(We0, 0);              // -> hA
    // layer 1 (shared weights)
    k_gemm<<<gemmGrid, 512>>>(0, Wq1, bq1, Wk1, bk1, Wv1, bv1, Ws1, bs1);
    k_agg<<<(NN + 7) / 8, 256>>>(We1, 1);              // -> hB
    // layer 2 (same weights)
    k_gemm<<<gemmGrid, 512>>>(1, Wq1, bq1, Wk1, bk1, Wv1, bv1, Ws1, bs1);
    k_agg<<<(NN + 7) / 8, 256>>>(We1, 0);              // -> hA

    // global add pool (segmented, batch sorted)
    k_pool<<<GG, CC>>>(0);

    // MLP head
    k_mlp1<<<(GG * L0 + 255) / 256, 256>>>(Wl0, bl0);
    k_mlp2<<<(GG * L1 + 255) / 256, 256>>>(Wl1, bl1);
    k_mlp3<<<1, 256>>>(Wl2, bl2, out);
}

// round 9
// speedup vs baseline: 1.3287x; 1.0099x over previous
#include <cuda_runtime.h>
#include <cuda_fp16.h>
#include <math_constants.h>

#define NN 50000
#define EE 800000
#define CC 128
#define GG 128
#define L0 512
#define L1 256

#define N4 (NN / 4)                 // 12500 int4 elements (NN divisible by 4)
#define SCAN_BLK 256
#define SCAN_NBLK ((N4 + SCAN_BLK - 1) / SCAN_BLK)   // 49

// ---------------- scratch (static device globals; no allocation) ----------------
__device__ float  g_q[(size_t)NN * CC];       // q per node (f32)
__device__ float  g_s[(size_t)NN * CC];       // skip (x@Ws+bs) per node (f32)
__device__ __half g_kvh[(size_t)NN * 256];    // k(128)|v(128) per node (f16)
__device__ float  g_hA[(size_t)NN * CC];
__device__ float  g_hB[(size_t)NN * CC];
__device__ int    g_cnt[NN];
__device__ int    g_off[NN + 4];              // padded for int4 store
__device__ int    g_cur[NN + 4];
__device__ int    g_bsum[SCAN_NBLK];
__device__ int    g_boff[SCAN_NBLK];
__device__ int    g_srcA[EE];
__device__ float4 g_eaC[EE];                  // edge_attr in CSR order (w unused)
__device__ int    g_gstart[GG + 1];
__device__ float  g_pool[GG * CC];
__device__ float  g_m1[GG * L0];
__device__ float  g_m2[GG * L1];

// ---------------- packed f32x2 helpers ----------------
__device__ __forceinline__ unsigned long long rep2(float x) {
    unsigned long long r;
    asm("mov.b64 %0, {%1, %1};" : "=l"(r) : "f"(x));
    return r;
}
#define FFMA_X2(acc, a, b) asm("fma.rn.f32x2 %0, %1, %2, %0;" : "+l"(acc) : "l"(a), "l"(b))

union U64F2 { unsigned long long u; float2 f; };

// ---------------- CSR build ----------------
__global__ void k_zero(const int* __restrict__ batch) {
    int i = blockIdx.x * blockDim.x + threadIdx.x;
    if (i < NN) g_cnt[i] = 0;
    if (i <= GG) {
        int lo = 0, hi = NN;
        while (lo < hi) {
            int mid = (lo + hi) >> 1;
            if (batch[mid] < i) lo = mid + 1; else hi = mid;
        }
        g_gstart[i] = lo;
    }
}

__global__ void k_count(const int* __restrict__ ei) {
    int e = blockIdx.x * blockDim.x + threadIdx.x;
    if (e < EE) atomicAdd(&g_cnt[ei[EE + e]], 1);
}

// ---- 3-kernel coalesced scan of g_cnt -> g_off/g_cur ----
__global__ void k_sum() {
    __shared__ int sh[SCAN_BLK];
    int t = threadIdx.x;
    int i4 = blockIdx.x * SCAN_BLK + t;
    int s = 0;
    if (i4 < N4) {
        int4 c = *(const int4*)&g_cnt[i4 * 4];
        s = c.x + c.y + c.z + c.w;
    }
    sh[t] = s;
    __syncthreads();
    for (int d = SCAN_BLK / 2; d > 0; d >>= 1) {
        if (t < d) sh[t] += sh[t + d];
        __syncthreads();
    }
    if (t == 0) g_bsum[blockIdx.x] = sh[0];
}

__global__ void k_bscan() {
    __shared__ int sh[64];
    int t = threadIdx.x;
    int v = (t < SCAN_NBLK) ? g_bsum[t] : 0;
    sh[t] = v;
    __syncthreads();
    for (int d = 1; d < 64; d <<= 1) {
        int u = (t >= d) ? sh[t - d] : 0;
        __syncthreads();
        sh[t] += u;
        __syncthreads();
    }
    if (t < SCAN_NBLK) g_boff[t] = sh[t] - v;   // exclusive
    if (t == 63) g_off[NN] = sh[63];            // total
}

__global__ void k_scat() {
    __shared__ int sh[SCAN_BLK];
    int t = threadIdx.x;
    int i4 = blockIdx.x * SCAN_BLK + t;
    int4 c = make_int4(0, 0, 0, 0);
    if (i4 < N4) c = *(const int4*)&g_cnt[i4 * 4];
    int s = c.x + c.y + c.z + c.w;
    sh[t] = s;
    __syncthreads();
    for (int d = 1; d < SCAN_BLK; d <<= 1) {
        int u = (t >= d) ? sh[t - d] : 0;
        __syncthreads();
        sh[t] += u;
        __syncthreads();
    }
    if (i4 < N4) {
        int base = g_boff[blockIdx.x] + sh[t] - s;   // exclusive prefix
        int4 o;
        o.x = base;
        o.y = base + c.x;
        o.z = o.y + c.y;
        o.w = o.z + c.z;
        *(int4*)&g_off[i4 * 4] = o;
        *(int4*)&g_cur[i4 * 4] = o;
    }
}

__global__ void k_fill(const int* __restrict__ ei, const float* __restrict__ ea) {
    int e = blockIdx.x * blockDim.x + threadIdx.x;
    if (e < EE) {
        int d = ei[EE + e];
        int p = atomicAdd(&g_cur[d], 1);
        g_srcA[p] = ei[e];
        float4 v;
        v.x = ea[e * 3 + 0]; v.y = ea[e * 3 + 1]; v.z = ea[e * 3 + 2]; v.w = 0.f;
        g_eaC[p] = v;
    }
}

// ---------------- layer-0 projection (din = 4) ----------------
__global__ void k_gemm0(const float* __restrict__ x,
                        const float* __restrict__ Wq, const float* __restrict__ bq,
                        const float* __restrict__ Wk, const float* __restrict__ bk,
                        const float* __restrict__ Wv, const float* __restrict__ bv,
                        const float* __restrict__ Ws, const float* __restrict__ bs) {
    long long idx = (long long)blockIdx.x * blockDim.x + threadIdx.x;
    if (idx >= (long long)NN * 512) return;
    int n = (int)(idx >> 9);
    int col = (int)(idx & 511);
    int grp = col >> 7;
    int c = col & 127;
    const float* W; const float* b;
    if      (grp == 0) { W = Wq; b = bq; }
    else if (grp == 1) { W = Wk; b = bk; }
    else if (grp == 2) { W = Wv; b = bv; }
    else               { W = Ws; b = bs; }
    float x0 = x[n * 4 + 0], x1 = x[n * 4 + 1], x2 = x[n * 4 + 2], x3 = x[n * 4 + 3];
    float v = b[c] + x0 * W[c] + x1 * W[128 + c] + x2 * W[256 + c] + x3 * W[384 + c];
    if      (grp == 0) g_q[(size_t)n * CC + c] = v;
    else if (grp == 1) g_kvh[(size_t)n * 256 + c] = __float2half_rn(v);
    else if (grp == 2) g_kvh[(size_t)n * 256 + 128 + c] = __float2half_rn(v);
    else               g_s[(size_t)n * CC + c] = v;
}

// ---------------- main projection GEMM: [NN,128] @ [128,128] x4 groups ----------------
// 128x128 tile, 512 threads, 8x4 microtile, BK=16, packed f32x2 FMA (M-pairs)
#define AS_STRIDE 132
__global__ __launch_bounds__(512) void k_gemm(int inSel,
                        const float* __restrict__ Wq, const float* __restrict__ bq,
                        const float* __restrict__ Wk, const float* __restrict__ bk,
                        const float* __restrict__ Wv, const float* __restrict__ bv,
                        const float* __restrict__ Ws, const float* __restrict__ bs) {
    const float* __restrict__ H = inSel ? g_hB : g_hA;
    __shared__ __align__(16) float As[16 * AS_STRIDE];  // [k][m], m=0..127
    __shared__ __align__(16) float Bs[16 * 128];        // [k][n], n=0..127

    int tid = threadIdx.x;
    int tx = tid & 31;          // 32 col groups of 4
    int ty = tid >> 5;          // 16 row groups of 8 (warp-uniform!)
    int row0 = blockIdx.y * 128;
    int grp = blockIdx.x;       // 0..3 : q,k,v,s
    const float* W; const float* b;
    if      (grp == 0) { W = Wq; b = bq; }
    else if (grp == 1) { W = Wk; b = bk; }
    else if (grp == 2) { W = Wv; b = bv; }
    else               { W = Ws; b = bs; }

    unsigned long long acc[4][4];   // [row-pair][col]; lo=row ty*8+2rp, hi=+1
#pragma unroll
    for (int i = 0; i < 4; i++)
#pragma unroll
        for (int j = 0; j < 4; j++) acc[i][j] = 0ULL;

    int am = tid >> 2;            // 0..127 row within tile
    int ak = (tid & 3) * 4;       // k offset (float4)
    int bkL = tid >> 5;           // 0..15
    int bnL = (tid & 31) * 4;     // 0..124

    for (int kk = 0; kk < 128; kk += 16) {
        // A tile transposed into As[k][m]
        float4 a4;
        if (row0 + am < NN)
            a4 = *(const float4*)&H[(size_t)(row0 + am) * 128 + kk + ak];
        else
            a4 = make_float4(0.f, 0.f, 0.f, 0.f);
        As[(ak + 0) * AS_STRIDE + am] = a4.x;
        As[(ak + 1) * AS_STRIDE + am] = a4.y;
        As[(ak + 2) * AS_STRIDE + am] = a4.z;
        As[(ak + 3) * AS_STRIDE + am] = a4.w;
        // B tile: 16 k x 128 n
        *(float4*)&Bs[bkL * 128 + bnL] = *(const float4*)&W[(size_t)(kk + bkL) * 128 + bnL];
        __syncthreads();
#pragma unroll
        for (int k = 0; k < 16; k++) {
            ulonglong2 a01 = *(const ulonglong2*)&As[k * AS_STRIDE + ty * 8];
            ulonglong2 a23 = *(const ulonglong2*)&As[k * AS_STRIDE + ty * 8 + 4];
            float4 b4 = *(const float4*)&Bs[k * 128 + tx * 4];
            unsigned long long ap[4] = {a01.x, a01.y, a23.x, a23.y};
            unsigned long long br[4] = {rep2(b4.x), rep2(b4.y), rep2(b4.z), rep2(b4.w)};
#pragma unroll
            for (int ip = 0; ip < 4; ip++)
#pragma unroll
                for (int j = 0; j < 4; j++) FFMA_X2(acc[ip][j], ap[ip], br[j]);
        }
        __syncthreads();
    }

    float4 bias = *(const float4*)&b[tx * 4];
    float bb[4] = {bias.x, bias.y, bias.z, bias.w};
#pragma unroll
    for (int ip = 0; ip < 4; ip++) {
        U64F2 c0, c1, c2, c3;
        c0.u = acc[ip][0]; c1.u = acc[ip][1]; c2.u = acc[ip][2]; c3.u = acc[ip][3];
#pragma unroll
        for (int half = 0; half < 2; half++) {
            int r = row0 + ty * 8 + 2 * ip + half;
            if (r >= NN) continue;
            float4 o;
            if (half == 0) {
                o.x = c0.f.x + bb[0]; o.y = c1.f.x + bb[1];
                o.z = c2.f.x + bb[2]; o.w = c3.f.x + bb[3];
            } else {
                o.x = c0.f.y + bb[0]; o.y = c1.f.y + bb[1];
                o.z = c2.f.y + bb[2]; o.w = c3.f.y + bb[3];
            }
            if (grp == 0) {
                *(float4*)&g_q[(size_t)r * CC + tx * 4] = o;
            } else if (grp == 3) {
                *(float4*)&g_s[(size_t)r * CC + tx * 4] = o;
            } else {
                __half2 h0 = __floats2half2_rn(o.x, o.y);
                __half2 h1 = __floats2half2_rn(o.z, o.w);
                uint2 u;
                u.x = *(unsigned int*)&h0;
                u.y = *(unsigned int*)&h1;
                size_t off = (size_t)r * 256 + (grp == 2 ? 128 : 0) + tx * 4;
                *(uint2*)&g_kvh[off] = u;
            }
        }
    }
}

// ---------------- edge aggregation: warp per dst node, online softmax ----------------
// Uses e = We.ea factorization: logit = (q.k + ea.t)/sqrt(C), t = We.q per node;
// out = sum(a*v) + We^T(sum(a*ea)).  k/v gathered in fp16.
__device__ __forceinline__ float4 ld_kv4(const __half* base, int idx) {
    uint2 u = *(const uint2*)(base + idx);
    __half2 h0 = *(__half2*)&u.x;
    __half2 h1 = *(__half2*)&u.y;
    float2 f0 = __half22float2(h0);
    float2 f1 = __half22float2(h1);
    return make_float4(f0.x, f0.y, f1.x, f1.y);
}

__global__ __launch_bounds__(256) void k_agg(const float* __restrict__ We,
                                             int outSel) {
    __shared__ float sWe[384];
    for (int i = threadIdx.x; i < 384; i += 256) sWe[i] = We[i];
    __syncthreads();

    int node = blockIdx.x * 8 + (threadIdx.x >> 5);
    if (node >= NN) return;
    int lane = threadIdx.x & 31;

    float4 qv = *(const float4*)&g_q[(size_t)node * CC + lane * 4];

    // t = We . q  (3 scalars, warp-reduced)
    float t0, t1, t2;
    {
        int c = lane * 4;
        t0 = sWe[c] * qv.x + sWe[c + 1] * qv.y + sWe[c + 2] * qv.z + sWe[c + 3] * qv.w;
        c += 128;
        t1 = sWe[c] * qv.x + sWe[c + 1] * qv.y + sWe[c + 2] * qv.z + sWe[c + 3] * qv.w;
        c += 128;
        t2 = sWe[c] * qv.x + sWe[c + 1] * qv.y + sWe[c + 2] * qv.z + sWe[c + 3] * qv.w;
#pragma unroll
        for (int o = 16; o > 0; o >>= 1) {
            t0 += __shfl_xor_sync(0xffffffffu, t0, o);
            t1 += __shfl_xor_sync(0xffffffffu, t1, o);
            t2 += __shfl_xor_sync(0xffffffffu, t2, o);
        }
    }

    float m = -CUDART_INF_F, den = 0.f;
    float4 acc = make_float4(0.f, 0.f, 0.f, 0.f);
    float s0 = 0.f, s1 = 0.f, s2 = 0.f;      // sum w*ea
    const float scale = 0.08838834764831845f; // 1/sqrt(128)

    int beg = __ldg(&g_off[node]), end = __ldg(&g_off[node + 1]);
    int p = beg;
    for (; p + 2 <= end; p += 2) {
        int n0 = __ldg(&g_srcA[p]), n1 = __ldg(&g_srcA[p + 1]);
        float4 ea0 = g_eaC[p], ea1 = g_eaC[p + 1];
        const __half* b0 = &g_kvh[(size_t)n0 * 256];
        const __half* b1 = &g_kvh[(size_t)n1 * 256];
        float4 kv0 = ld_kv4(b0, lane * 4);
        float4 vv0 = ld_kv4(b0, 128 + lane * 4);
        float4 kv1 = ld_kv4(b1, lane * 4);
        float4 vv1 = ld_kv4(b1, 128 + lane * 4);
        float d0 = qv.x * kv0.x + qv.y * kv0.y + qv.z * kv0.z + qv.w * kv0.w;
        float d1 = qv.x * kv1.x + qv.y * kv1.y + qv.z * kv1.z + qv.w * kv1.w;
#pragma unroll
        for (int o = 16; o > 0; o >>= 1) {
            d0 += __shfl_xor_sync(0xffffffffu, d0, o);
            d1 += __shfl_xor_sync(0xffffffffu, d1, o);
        }
        float l0 = (d0 + ea0.x * t0 + ea0.y * t1 + ea0.z * t2) * scale;
        float l1 = (d1 + ea1.x * t0 + ea1.y * t1 + ea1.z * t2) * scale;
        float nm = fmaxf(m, fmaxf(l0, l1));
        float corr = __expf(m - nm);
        float w0 = __expf(l0 - nm);
        float w1 = __expf(l1 - nm);
        den = den * corr + w0 + w1;
        acc.x = acc.x * corr + w0 * vv0.x + w1 * vv1.x;
        acc.y = acc.y * corr + w0 * vv0.y + w1 * vv1.y;
        acc.z = acc.z * corr + w0 * vv0.z + w1 * vv1.z;
        acc.w = acc.w * corr + w0 * vv0.w + w1 * vv1.w;
        s0 = s0 * corr + w0 * ea0.x + w1 * ea1.x;
        s1 = s1 * corr + w0 * ea0.y + w1 * ea1.y;
        s2 = s2 * corr + w0 * ea0.z + w1 * ea1.z;
        m = nm;
    }
    if (p < end) {
        int n0 = __ldg(&g_srcA[p]);
        float4 ea0 = g_eaC[p];
        const __half* b0 = &g_kvh[(size_t)n0 * 256];
        float4 kv0 = ld_kv4(b0, lane * 4);
        float4 vv0 = ld_kv4(b0, 128 + lane * 4);
        float d0 = qv.x * kv0.x + qv.y * kv0.y + qv.z * kv0.z + qv.w * kv0.w;
#pragma unroll
        for (int o = 16; o > 0; o >>= 1) d0 += __shfl_xor_sync(0xffffffffu, d0, o);
        float l0 = (d0 + ea0.x * t0 + ea0.y * t1 + ea0.z * t2) * scale;
        float nm = fmaxf(m, l0);
        float corr = __expf(m - nm);
        float w0 = __expf(l0 - nm);
        den = den * corr + w0;
        acc.x = acc.x * corr + w0 * vv0.x;
        acc.y = acc.y * corr + w0 * vv0.y;
        acc.z = acc.z * corr + w0 * vv0.z;
        acc.w = acc.w * corr + w0 * vv0.w;
        s0 = s0 * corr + w0 * ea0.x;
        s1 = s1 * corr + w0 * ea0.y;
        s2 = s2 * corr + w0 * ea0.z;
        m = nm;
    }

    float inv = den > 0.f ? 1.f / den : 0.f;
    s0 *= inv; s1 *= inv; s2 *= inv;
    float4 skip = *(const float4*)&g_s[(size_t)node * CC + lane * 4];
    int c = lane * 4;
    float4 o;
    o.x = acc.x * inv + s0 * sWe[c + 0] + s1 * sWe[128 + c + 0] + s2 * sWe[256 + c + 0] + skip.x;
    o.y = acc.y * inv + s0 * sWe[c + 1] + s1 * sWe[128 + c + 1] + s2 * sWe[256 + c + 1] + skip.y;
    o.z = acc.z * inv + s0 * sWe[c + 2] + s1 * sWe[128 + c + 2] + s2 * sWe[256 + c + 2] + skip.z;
    o.w = acc.w * inv + s0 * sWe[c + 3] + s1 * sWe[128 + c + 3] + s2 * sWe[256 + c + 3] + skip.w;
    o.x = o.x > 0.f ? o.x : 0.01f * o.x;
    o.y = o.y > 0.f ? o.y : 0.01f * o.y;
    o.z = o.z > 0.f ? o.z : 0.01f * o.z;
    o.w = o.w > 0.f ? o.w : 0.01f * o.w;
    float* __restrict__ out = outSel ? g_hB : g_hA;
    *(float4*)&out[(size_t)node * CC + c] = o;
}

// ---------------- pooling: batch is sorted -> segmented sum, no atomics ----------------
__global__ void k_pool(int hSel) {
    int g = blockIdx.x;       // graph
    int c = threadIdx.x;      // channel
    const float* h = hSel ? g_hB : g_hA;
    int s = g_gstart[g], e = g_gstart[g + 1];
    float acc = 0.f;
    for (int n = s; n < e; n++) acc += h[(size_t)n * CC + c];
    g_pool[g * CC + c] = acc;
}

// ---------------- MLP head ----------------
__global__ void k_mlp1(const float* __restrict__ W, const float* __restrict__ b) {
    int idx = blockIdx.x * blockDim.x + threadIdx.x;
    if (idx >= GG * L0) return;
    int r = idx >> 9, c = idx & (L0 - 1);
    float s = b[c];
    for (int k = 0; k < CC; k++) s += g_pool[r * CC + k] * W[k * L0 + c];
    g_m1[idx] = s > 0.f ? s : 0.f;
}

__global__ void k_mlp2(const float* __restrict__ W, const float* __restrict__ b) {
    int idx = blockIdx.x * blockDim.x + threadIdx.x;
    if (idx >= GG * L1) return;
    int r = idx >> 8, c = idx & (L1 - 1);
    float s = b[c];
    for (int k = 0; k < L0; k++) s += g_m1[r * L0 + k] * W[k * L1 + c];
    g_m2[idx] = s > 0.f ? s : 0.f;
}

__global__ void k_mlp3(const float* __restrict__ W, const float* __restrict__ b,
                       float* __restrict__ out) {
    int idx = threadIdx.x;
    if (idx >= GG * 2) return;
    int r = idx >> 1, c = idx & 1;
    float s = b[c];
    for (int k = 0; k < L1; k++) s += g_m2[r * L1 + k] * W[k * 2 + c];
    out[idx] = s;
}

// ---------------- launch ----------------
extern "C" void kernel_launch(void* const* d_in, const int* in_sizes, int n_in,
                              void* d_out, int out_size) {
    const float* x     = (const float*)d_in[0];
    const int*   ei    = (const int*)d_in[1];
    const float* ea    = (const float*)d_in[2];
    const int*   batch = (const int*)d_in[3];
    const float* Wq0 = (const float*)d_in[4];  const float* bq0 = (const float*)d_in[5];
    const float* Wk0 = (const float*)d_in[6];  const float* bk0 = (const float*)d_in[7];
    const float* Wv0 = (const float*)d_in[8];  const float* bv0 = (const float*)d_in[9];
    const float* We0 = (const float*)d_in[10];
    const float* Ws0 = (const float*)d_in[11]; const float* bs0 = (const float*)d_in[12];
    const float* Wq1 = (const float*)d_in[13]; const float* bq1 = (const float*)d_in[14];
    const float* Wk1 = (const float*)d_in[15]; const float* bk1 = (const float*)d_in[16];
    const float* Wv1 = (const float*)d_in[17]; const float* bv1 = (const float*)d_in[18];
    const float* We1 = (const float*)d_in[19];
    const float* Ws1 = (const float*)d_in[20]; const float* bs1 = (const float*)d_in[21];
    const float* Wl0 = (const float*)d_in[22]; const float* bl0 = (const float*)d_in[23];
    const float* Wl1 = (const float*)d_in[24]; const float* bl1 = (const float*)d_in[25];
    const float* Wl2 = (const float*)d_in[26]; const float* bl2 = (const float*)d_in[27];
    float* out = (float*)d_out;

    // CSR build (by dst) + graph starts
    k_zero<<<(NN + 255) / 256, 256>>>(batch);
    k_count<<<(EE + 255) / 256, 256>>>(ei);
    k_sum<<<SCAN_NBLK, SCAN_BLK>>>();
    k_bscan<<<1, 64>>>();
    k_scat<<<SCAN_NBLK, SCAN_BLK>>>();
    k_fill<<<(EE + 255) / 256, 256>>>(ei, ea);

    dim3 gemmGrid(4, (NN + 127) / 128);

    // layer 0
    k_gemm0<<<(int)(((long long)NN * 512 + 255) / 256), 256>>>(x, Wq0, bq0, Wk0, bk0, Wv0, bv0, Ws0, bs0);
    k_agg<<<(NN + 7) / 8, 256>>>(We0, 0);              // -> hA
    // layer 1 (shared weights)
    k_gemm<<<gemmGrid, 512>>>(0, Wq1, bq1, Wk1, bk1, Wv1, bv1, Ws1, bs1);
    k_agg<<<(NN + 7) / 8, 256>>>(We1, 1);              // -> hB
    // layer 2 (same weights)
    k_gemm<<<gemmGrid, 512>>>(1, Wq1, bq1, Wk1, bk1, Wv1, bv1, Ws1, bs1);
    k_agg<<<(NN + 7) / 8, 256>>>(We1, 0);              // -> hA

    // global add pool (segmented, batch sorted)
    k_pool<<<GG, CC>>>(0);

    // MLP head
    k_mlp1<<<(GG * L0 + 255) / 256, 256>>>(Wl0, bl0);
    k_mlp2<<<(GG * L1 + 255) / 256, 256>>>(Wl1, bl1);
    k_mlp3<<<1, 256>>>(Wl2, bl2, out);
}